// round 7
// baseline (speedup 1.0000x reference)
#include <cuda_runtime.h>
#include <math.h>

// ---------------- problem constants ----------------
#define BB 4
#define LL 5
#define HW 1024          // HS*WS
#define CC 256
#define MM 8
#define DD 32
#define TT 2
#define II 256           // M*D
#define NTOK (BB*LL*HW)  // 20480
#define TOKELEMS (NTOK*CC)

// ---------------- scratch (static device globals) ----------------
__device__ __align__(16) float g_xn[TOKELEMS];   // tf32-rounded LN output
__device__ __align__(16) float g_q [TOKELEMS];
__device__ __align__(16) float g_k [TOKELEMS];
__device__ __align__(16) float g_v [TOKELEMS];
__device__ __align__(16) float g_ao[TOKELEMS];   // tf32-rounded attn output
__device__ __align__(16) float g_wq[TT*CC*II];   // tf32-rounded weights
__device__ __align__(16) float g_wk[TT*CC*II];
__device__ __align__(16) float g_wv[TT*CC*II];
__device__ __align__(16) float g_wa[TT*II*CC];

// ---------------- helpers ----------------
__device__ __forceinline__ unsigned f2tf(float f) {
    unsigned u;
    asm("cvt.rna.tf32.f32 %0, %1;" : "=r"(u) : "f"(f));
    return u;
}
__device__ __forceinline__ float f2tf_f(float f) { return __uint_as_float(f2tf(f)); }

__device__ __forceinline__ void mma_tf32(float c[4],
                                         unsigned a0, unsigned a1, unsigned a2, unsigned a3,
                                         unsigned b0, unsigned b1)
{
    asm volatile(
        "mma.sync.aligned.m16n8k8.row.col.f32.tf32.tf32.f32 "
        "{%0,%1,%2,%3}, {%4,%5,%6,%7}, {%8,%9}, {%0,%1,%2,%3};"
        : "+f"(c[0]), "+f"(c[1]), "+f"(c[2]), "+f"(c[3])
        : "r"(a0), "r"(a1), "r"(a2), "r"(a3), "r"(b0), "r"(b1));
}

__device__ __forceinline__ void cpa16(float* dst, const float* src) {
    unsigned d = (unsigned)__cvta_generic_to_shared(dst);
    asm volatile("cp.async.cg.shared.global [%0], [%1], 16;" :: "r"(d), "l"(src));
}
__device__ __forceinline__ void cpa_commit() {
    asm volatile("cp.async.commit_group;" ::: "memory");
}
template <int N> __device__ __forceinline__ void cpa_wait() {
    asm volatile("cp.async.wait_group %0;" :: "n"(N) : "memory");
}

// =====================================================================
// Kernel 0: round all weight tensors to tf32 once per launch (values
// identical to rounding inside the GEMM; enables raw cp.async there).
// grid = (128, 4), 256 threads; each thread converts one float4.
// =====================================================================
__global__ __launch_bounds__(256) void k_cvtw(const float* __restrict__ Wq,
                                              const float* __restrict__ Wk,
                                              const float* __restrict__ Wv,
                                              const float* __restrict__ Wa)
{
    const float* src;
    float* dst;
    switch (blockIdx.y) {
        case 0: src = Wq; dst = g_wq; break;
        case 1: src = Wk; dst = g_wk; break;
        case 2: src = Wv; dst = g_wv; break;
        default: src = Wa; dst = g_wa; break;
    }
    int idx = blockIdx.x * 256 + threadIdx.x;   // 0..32767 float4 slots
    float4 v = reinterpret_cast<const float4*>(src)[idx];
    v.x = f2tf_f(v.x); v.y = f2tf_f(v.y); v.z = f2tf_f(v.z); v.w = f2tf_f(v.w);
    reinterpret_cast<float4*>(dst)[idx] = v;
}

// =====================================================================
// Kernel 1: LayerNorm over C=256, one warp per token; output tf32-rounded.
// =====================================================================
__global__ __launch_bounds__(256) void k_ln(const float* __restrict__ x,
                                            const float* __restrict__ lw,
                                            const float* __restrict__ lb)
{
    int warp = threadIdx.x >> 5;
    int lane = threadIdx.x & 31;
    int tok  = (blockIdx.x << 3) + warp;

    const float4* xr = reinterpret_cast<const float4*>(x + (size_t)tok * CC);
    float4 v0 = xr[lane];
    float4 v1 = xr[lane + 32];

    float s  = v0.x + v0.y + v0.z + v0.w + v1.x + v1.y + v1.z + v1.w;
    float sq = v0.x*v0.x + v0.y*v0.y + v0.z*v0.z + v0.w*v0.w
             + v1.x*v1.x + v1.y*v1.y + v1.z*v1.z + v1.w*v1.w;
    #pragma unroll
    for (int off = 16; off >= 1; off >>= 1) {
        s  += __shfl_xor_sync(0xffffffffu, s,  off);
        sq += __shfl_xor_sync(0xffffffffu, sq, off);
    }
    float mean = s * (1.0f / 256.0f);
    float var  = sq * (1.0f / 256.0f) - mean * mean;
    float rstd = rsqrtf(var + 1e-5f);

    const float4* w4 = reinterpret_cast<const float4*>(lw);
    const float4* b4 = reinterpret_cast<const float4*>(lb);
    float4 w0 = w4[lane], w1 = w4[lane + 32];
    float4 b0 = b4[lane], b1 = b4[lane + 32];

    float4 o0, o1;
    o0.x = f2tf_f((v0.x - mean) * rstd * w0.x + b0.x);
    o0.y = f2tf_f((v0.y - mean) * rstd * w0.y + b0.y);
    o0.z = f2tf_f((v0.z - mean) * rstd * w0.z + b0.z);
    o0.w = f2tf_f((v0.w - mean) * rstd * w0.w + b0.w);
    o1.x = f2tf_f((v1.x - mean) * rstd * w1.x + b1.x);
    o1.y = f2tf_f((v1.y - mean) * rstd * w1.y + b1.y);
    o1.z = f2tf_f((v1.z - mean) * rstd * w1.z + b1.z);
    o1.w = f2tf_f((v1.w - mean) * rstd * w1.w + b1.w);

    float4* orow = reinterpret_cast<float4*>(g_xn + (size_t)tok * CC);
    orow[lane]      = o0;
    orow[lane + 32] = o1;
}

// =====================================================================
// tf32 GEMM tile via cp.async double buffer, BK=16, STATIC shared memory
// (37.9 KB -> no cudaFuncSetAttribute needed, 2 CTAs/SM).
// Out[128x128] = A[128x256] * W[256x128] + bias.
// A row-major in smem (pad 20), B [k][n] (pad 136). 8 warps, 64x32/warp.
// Operands already tf32-rounded in gmem -> raw 16B cp.async.
// =====================================================================
#define AS_ST 20
#define BS_ST 136
#define AS_SZ (128 * AS_ST)        // 2560 floats per stage
#define BS_SZ (16 * BS_ST)         // 2176 floats per stage

__device__ __forceinline__ void gemm_tf32(const float* __restrict__ A,
                                          const float* __restrict__ W,
                                          const float* __restrict__ bias,
                                          float* __restrict__ Out,
                                          int m0, int ncol0)
{
    __shared__ __align__(16) float As[2 * AS_SZ];   // [2][128][20]
    __shared__ __align__(16) float Bs[2 * BS_SZ];   // [2][16][136]

    const int tid  = threadIdx.x;
    const int lane = tid & 31;
    const int warp = tid >> 5;
    const int wm = (warp >> 2) << 6;   // 0 or 64
    const int wn = (warp & 3)  << 5;   // 0,32,64,96

    // loader index precompute (2 A + 2 B 16-byte chunks per thread)
    int arow[2], ac4[2], brow[2], bc4[2];
    #pragma unroll
    for (int it = 0; it < 2; ++it) {
        int pos = tid + (it << 8);
        arow[it] = pos >> 2;  ac4[it] = (pos & 3) << 2;    // row 0..127, col 0/4/8/12
        brow[it] = pos >> 5;  bc4[it] = (pos & 31) << 2;   // row 0..15,  col 0..124
    }

    float acc[4][4][4];
    #pragma unroll
    for (int mt = 0; mt < 4; ++mt)
        #pragma unroll
        for (int nt = 0; nt < 4; ++nt)
            #pragma unroll
            for (int r = 0; r < 4; ++r) acc[mt][nt][r] = 0.0f;

    // ---- prologue: stage chunk 0 into buf 0 ----
    #pragma unroll
    for (int it = 0; it < 2; ++it) {
        cpa16(As + arow[it] * AS_ST + ac4[it],
              A + (size_t)(m0 + arow[it]) * 256 + ac4[it]);
        cpa16(Bs + brow[it] * BS_ST + bc4[it],
              W + (size_t)brow[it] * 256 + ncol0 + bc4[it]);
    }
    cpa_commit();

    for (int ch = 0; ch < 16; ++ch) {
        int buf = ch & 1;
        if (ch < 15) {
            int kc = (ch + 1) << 4;
            float* Asn = As + (buf ^ 1) * AS_SZ;
            float* Bsn = Bs + (buf ^ 1) * BS_SZ;
            #pragma unroll
            for (int it = 0; it < 2; ++it) {
                cpa16(Asn + arow[it] * AS_ST + ac4[it],
                      A + (size_t)(m0 + arow[it]) * 256 + kc + ac4[it]);
                cpa16(Bsn + brow[it] * BS_ST + bc4[it],
                      W + (size_t)(kc + brow[it]) * 256 + ncol0 + bc4[it]);
            }
            cpa_commit();
            cpa_wait<1>();
        } else {
            cpa_wait<0>();
        }
        __syncthreads();

        const float* Asb = As + buf * AS_SZ;
        const float* Bsb = Bs + buf * BS_SZ;

        #pragma unroll
        for (int ks = 0; ks < 2; ++ks) {
            int kr = (ks << 3) + (lane & 3);
            unsigned afr[4][4], bfr[4][2];
            #pragma unroll
            for (int mt = 0; mt < 4; ++mt) {
                int mc = wm + (mt << 4) + (lane >> 2);
                afr[mt][0] = __float_as_uint(Asb[mc * AS_ST + kr]);
                afr[mt][1] = __float_as_uint(Asb[(mc + 8) * AS_ST + kr]);
                afr[mt][2] = __float_as_uint(Asb[mc * AS_ST + kr + 4]);
                afr[mt][3] = __float_as_uint(Asb[(mc + 8) * AS_ST + kr + 4]);
            }
            #pragma unroll
            for (int nt = 0; nt < 4; ++nt) {
                int nc = wn + (nt << 3) + (lane >> 2);
                bfr[nt][0] = __float_as_uint(Bsb[kr * BS_ST + nc]);
                bfr[nt][1] = __float_as_uint(Bsb[(kr + 4) * BS_ST + nc]);
            }
            #pragma unroll
            for (int mt = 0; mt < 4; ++mt)
                #pragma unroll
                for (int nt = 0; nt < 4; ++nt)
                    mma_tf32(acc[mt][nt],
                             afr[mt][0], afr[mt][1], afr[mt][2], afr[mt][3],
                             bfr[nt][0], bfr[nt][1]);
        }
        __syncthreads();
    }

    // ---- epilogue: + bias ----
    #pragma unroll
    for (int mt = 0; mt < 4; ++mt) {
        int mrow = m0 + wm + (mt << 4) + (lane >> 2);
        #pragma unroll
        for (int nt = 0; nt < 4; ++nt) {
            int nc = ncol0 + wn + (nt << 3) + ((lane & 3) << 1);
            float b0 = bias[nc], b1 = bias[nc + 1];
            float2 r0, r1;
            r0.x = acc[mt][nt][0] + b0; r0.y = acc[mt][nt][1] + b1;
            r1.x = acc[mt][nt][2] + b0; r1.y = acc[mt][nt][3] + b1;
            *reinterpret_cast<float2*>(Out + (size_t)mrow * 256 + nc)       = r0;
            *reinterpret_cast<float2*>(Out + (size_t)(mrow + 8) * 256 + nc) = r1;
        }
    }
}

// =====================================================================
// Kernel 2: fused Q/K/V projection. grid = (8 mtiles, 6 sel*ntile, 20 bl)
// =====================================================================
__global__ __launch_bounds__(256, 2) void k_gemm_qkv(const float* __restrict__ pe,
                                                     const float* __restrict__ bq,
                                                     const float* __restrict__ bk,
                                                     const float* __restrict__ bv)
{
    int bl = blockIdx.z;
    int t  = (int)pe[(size_t)bl * 3072 + 2];
    int sel   = blockIdx.y >> 1;
    int ncol0 = (blockIdx.y & 1) << 7;

    const float* W;
    const float* bias;
    float* out;
    if (sel == 0)      { W = g_wq; bias = bq; out = g_q; }
    else if (sel == 1) { W = g_wk; bias = bk; out = g_k; }
    else               { W = g_wv; bias = bv; out = g_v; }

    gemm_tf32(g_xn + (size_t)bl * HW * CC,
              W + (size_t)t * CC * II,
              bias + (size_t)t * II,
              out + (size_t)bl * HW * II,
              blockIdx.x << 7, ncol0);
}

// =====================================================================
// Kernel 3: fused HGT attention. 512 threads = 16 warps = 16 hw per block.
// k/v in registers + shfl broadcast. grid = B*M*(HW/16) = 2048.
// Output tf32-rounded.
// =====================================================================
__global__ __launch_bounds__(512) void k_attn(const int*   __restrict__ mask,
                                              const float* __restrict__ pe,
                                              const float* __restrict__ rel_att,
                                              const float* __restrict__ rel_msg)
{
    __shared__ float Wa_s[4][33 * 32];   // [r][q*33 + p] (transposed)
    __shared__ float Wm_s[4][33 * 32];   // [r][p*33 + c]
    __shared__ int   ts_s[LL];

    int tid  = threadIdx.x;
    int lane = tid & 31;
    int w    = tid >> 5;                 // 0..15
    int bidx = blockIdx.x;
    int hw   = ((bidx & 63) << 4) + w;
    int m    = (bidx >> 6) & 7;
    int b    = bidx >> 9;

    if (tid < LL) ts_s[tid] = (int)pe[(size_t)(b * LL + tid) * 3072 + 2];

    for (int idx = tid; idx < 4096; idx += 512) {
        int r   = idx >> 10;
        int rem = idx & 1023;
        int p   = rem >> 5;
        int qq  = rem & 31;
        size_t goff = (size_t)(r * MM + m) * 1024 + rem;
        Wa_s[r][qq * 33 + p] = rel_att[goff];
        Wm_s[r][p * 33 + qq] = rel_msg[goff];
    }

    float qreg[LL], kreg[LL], vreg[LL];
    int base_off = (m << 5) + lane;
    #pragma unroll
    for (int j = 0; j < LL; ++j) {
        size_t tok = (size_t)((b * LL + j) << 10) + hw;
        qreg[j] = g_q[tok * II + base_off];
        kreg[j] = g_k[tok * II + base_off];
        vreg[j] = g_v[tok * II + base_off];
    }
    __syncthreads();

    // relation transforms via shfl broadcast of k/v elements
    float kp[LL][2], vp[LL][2];
    #pragma unroll
    for (int j = 0; j < LL; ++j) {
        int tj = ts_s[j];
        const float* WA0 = Wa_s[tj];
        const float* WA1 = Wa_s[2 + tj];
        const float* WM0 = Wm_s[tj];
        const float* WM1 = Wm_s[2 + tj];
        float a0 = 0.f, a1 = 0.f, s0 = 0.f, s1 = 0.f;
        #pragma unroll
        for (int qq = 0; qq < 32; ++qq) {
            float kv = __shfl_sync(0xffffffffu, kreg[j], qq);
            float vv = __shfl_sync(0xffffffffu, vreg[j], qq);
            int off = qq * 33 + lane;
            a0 = fmaf(WA0[off], kv, a0);
            a1 = fmaf(WA1[off], kv, a1);
            s0 = fmaf(WM0[off], vv, s0);
            s1 = fmaf(WM1[off], vv, s1);
        }
        kp[j][0] = a0; kp[j][1] = a1;
        vp[j][0] = s0; vp[j][1] = s1;
    }

    // att[i][j] = scale * q_i . k'_{j, t_i}
    float att[LL][LL];
    #pragma unroll
    for (int i = 0; i < LL; ++i) {
        int ti = ts_s[i];
        #pragma unroll
        for (int j = 0; j < LL; ++j) {
            float kpv  = ti ? kp[j][1] : kp[j][0];
            float part = qreg[i] * kpv;
            part += __shfl_xor_sync(0xffffffffu, part, 16);
            part += __shfl_xor_sync(0xffffffffu, part, 8);
            part += __shfl_xor_sync(0xffffffffu, part, 4);
            part += __shfl_xor_sync(0xffffffffu, part, 2);
            part += __shfl_xor_sync(0xffffffffu, part, 1);
            att[i][j] = part * 0.17677669529663687f;   // D^-0.5
        }
    }

    // mask + softmax + weighted message + tf32-rounded store
    const int* mrow = mask + ((size_t)(b << 10) + hw) * 25;
    #pragma unroll
    for (int i = 0; i < LL; ++i) {
        float mx = -1e30f;
        #pragma unroll
        for (int j = 0; j < LL; ++j) {
            if (mrow[i * 5 + j] == 0) att[i][j] = -1e9f;
            mx = fmaxf(mx, att[i][j]);
        }
        float s = 0.f;
        #pragma unroll
        for (int j = 0; j < LL; ++j) {
            float e = __expf(att[i][j] - mx);
            att[i][j] = e;
            s += e;
        }
        float inv = 1.0f / s;
        int ti = ts_s[i];
        float o = 0.f;
        #pragma unroll
        for (int j = 0; j < LL; ++j) {
            float vpv = ti ? vp[j][1] : vp[j][0];
            o = fmaf(att[i][j], vpv, o);
        }
        size_t tok = (size_t)((b * LL + i) << 10) + hw;
        g_ao[tok * II + base_off] = f2tf_f(o * inv);
    }
}

// =====================================================================
// Kernel 4: output projection + bias -> final output. grid = (8,2,20)
// =====================================================================
__global__ __launch_bounds__(256, 2) void k_gemm_ao(const float* __restrict__ pe,
                                                    const float* __restrict__ ba,
                                                    float* __restrict__ out)
{
    int bl = blockIdx.z;
    int t  = (int)pe[(size_t)bl * 3072 + 2];
    gemm_tf32(g_ao + (size_t)bl * HW * II,
              g_wa + (size_t)t * II * CC,
              ba + (size_t)t * CC,
              out + (size_t)bl * HW * CC,
              blockIdx.x << 7, (blockIdx.y & 1) << 7);
}

// =====================================================================
extern "C" void kernel_launch(void* const* d_in, const int* in_sizes, int n_in,
                              void* d_out, int out_size)
{
    const float* x    = (const float*)d_in[0];
    const int*   mask = (const int*)  d_in[1];
    const float* pe   = (const float*)d_in[2];
    const float* lnw  = (const float*)d_in[3];
    const float* lnb  = (const float*)d_in[4];
    const float* Wq   = (const float*)d_in[5];
    const float* bq   = (const float*)d_in[6];
    const float* Wk   = (const float*)d_in[7];
    const float* bk   = (const float*)d_in[8];
    const float* Wv   = (const float*)d_in[9];
    const float* bv   = (const float*)d_in[10];
    const float* Wa   = (const float*)d_in[11];
    const float* ba   = (const float*)d_in[12];
    const float* ra   = (const float*)d_in[13];
    const float* rm   = (const float*)d_in[14];
    float* out = (float*)d_out;

    dim3 gw(128, 4);
    k_cvtw<<<gw, 256>>>(Wq, Wk, Wv, Wa);

    k_ln<<<2560, 256>>>(x, lnw, lnb);

    dim3 g1(8, 6, 20);
    k_gemm_qkv<<<g1, 256>>>(pe, bq, bk, bv);

    k_attn<<<2048, 512>>>(mask, pe, ra, rm);

    dim3 g2(8, 2, 20);
    k_gemm_ao<<<g2, 256>>>(pe, ba, out);
}

// round 8
// speedup vs baseline: 1.3689x; 1.3689x over previous
#include <cuda_runtime.h>
#include <math.h>

// ---------------- problem constants ----------------
#define BB 4
#define LL 5
#define HW 1024          // HS*WS
#define CC 256
#define MM 8
#define DD 32
#define TT 2
#define II 256           // M*D
#define NTOK (BB*LL*HW)  // 20480
#define TOKELEMS (NTOK*CC)

// ---------------- scratch (static device globals) ----------------
__device__ __align__(16) float g_xn[TOKELEMS];      // tf32-rounded LN output
__device__ __align__(16) float g_q [TOKELEMS];
__device__ __align__(16) float g_kp[2*TOKELEMS];    // transformed K, ti=0/1
__device__ __align__(16) float g_vp[2*TOKELEMS];    // transformed V, ti=0/1
__device__ __align__(16) float g_ao[TOKELEMS];      // tf32-rounded attn output
__device__ __align__(16) float g_wq [TT*CC*II];     // tf32-rounded Wq
__device__ __align__(16) float g_wa [TT*II*CC];     // tf32-rounded Wa (out proj)
__device__ __align__(16) float g_wkc[4*CC*II];      // combined K weights [e'][c][i]
__device__ __align__(16) float g_wvc[4*CC*II];      // combined V weights
__device__ float g_bkc[4*II];                       // combined K bias
__device__ float g_bvc[4*II];                       // combined V bias

// ---------------- helpers ----------------
__device__ __forceinline__ unsigned f2tf(float f) {
    unsigned u;
    asm("cvt.rna.tf32.f32 %0, %1;" : "=r"(u) : "f"(f));
    return u;
}
__device__ __forceinline__ float f2tf_f(float f) { return __uint_as_float(f2tf(f)); }

__device__ __forceinline__ void mma_tf32(float c[4],
                                         unsigned a0, unsigned a1, unsigned a2, unsigned a3,
                                         unsigned b0, unsigned b1)
{
    asm volatile(
        "mma.sync.aligned.m16n8k8.row.col.f32.tf32.tf32.f32 "
        "{%0,%1,%2,%3}, {%4,%5,%6,%7}, {%8,%9}, {%0,%1,%2,%3};"
        : "+f"(c[0]), "+f"(c[1]), "+f"(c[2]), "+f"(c[3])
        : "r"(a0), "r"(a1), "r"(a2), "r"(a3), "r"(b0), "r"(b1));
}

__device__ __forceinline__ void cpa16(float* dst, const float* src) {
    unsigned d = (unsigned)__cvta_generic_to_shared(dst);
    asm volatile("cp.async.cg.shared.global [%0], [%1], 16;" :: "r"(d), "l"(src));
}
__device__ __forceinline__ void cpa_commit() {
    asm volatile("cp.async.commit_group;" ::: "memory");
}
template <int N> __device__ __forceinline__ void cpa_wait() {
    asm volatile("cp.async.wait_group %0;" :: "n"(N) : "memory");
}

// =====================================================================
// Kernel 0a: round Wq / Wa to tf32. grid = (128, 2), 256 threads.
// =====================================================================
__global__ __launch_bounds__(256) void k_cvtw(const float* __restrict__ Wq,
                                              const float* __restrict__ Wa)
{
    const float* src = blockIdx.y ? Wa : Wq;
    float* dst       = blockIdx.y ? g_wa : g_wq;
    int idx = blockIdx.x * 256 + threadIdx.x;   // 0..32767 float4 slots
    float4 v = reinterpret_cast<const float4*>(src)[idx];
    v.x = f2tf_f(v.x); v.y = f2tf_f(v.y); v.z = f2tf_f(v.z); v.w = f2tf_f(v.w);
    reinterpret_cast<float4*>(dst)[idx] = v;
}

// =====================================================================
// Kernel 0b: build combined weights.
//  K: WkC[e'][c][m*32+p] = s * sum_q Wk[tj][c][m*32+q] * RA[e'][m][p][q]
//  V: WvC[e'][c][m*32+o] =     sum_p Wv[tj][c][m*32+p] * RM[e'][m][p][o]
//  (e' = ti*2+tj, tj = e'&1; s = D^-0.5 folded into K side; biases likewise)
// grid = (e'=4, m=8, kind=2), 256 threads.
// =====================================================================
__global__ __launch_bounds__(256) void k_comb(const float* __restrict__ Wk,
                                              const float* __restrict__ bk,
                                              const float* __restrict__ Wv,
                                              const float* __restrict__ bv,
                                              const float* __restrict__ ra,
                                              const float* __restrict__ rm)
{
    __shared__ float R[32][33];
    __shared__ float brow[32];

    int e    = blockIdx.x;
    int m    = blockIdx.y;
    int kind = blockIdx.z;      // 0 = K(att), 1 = V(msg)
    int tj   = e & 1;
    int tid  = threadIdx.x;

    const float* Rsrc = (kind == 0 ? ra : rm) + (size_t)(e * MM + m) * 1024;
    for (int idx = tid; idx < 1024; idx += 256)
        R[idx >> 5][idx & 31] = Rsrc[idx];
    const float* bsrc = (kind == 0 ? bk : bv) + tj * II;
    if (tid < 32) brow[tid] = bsrc[m * 32 + tid];
    __syncthreads();

    const float scale = kind == 0 ? 0.17677669529663687f : 1.0f;
    const float* Wsrc = (kind == 0 ? Wk : Wv) + (size_t)tj * CC * II;
    float* dstW = (kind == 0 ? g_wkc : g_wvc) + (size_t)e * CC * II;

    float wrow[32];
    #pragma unroll
    for (int i = 0; i < 32; ++i)
        wrow[i] = Wsrc[(size_t)tid * II + m * 32 + i];

    #pragma unroll
    for (int o = 0; o < 32; ++o) {
        float s = 0.f;
        #pragma unroll
        for (int i = 0; i < 32; ++i)
            s = fmaf(wrow[i], kind == 0 ? R[o][i] : R[i][o], s);
        dstW[(size_t)tid * II + m * 32 + o] = f2tf_f(s * scale);
    }

    if (tid < 32) {
        float s = 0.f;
        #pragma unroll
        for (int i = 0; i < 32; ++i)
            s = fmaf(brow[i], kind == 0 ? R[tid][i] : R[i][tid], s);
        float* dstB = (kind == 0 ? g_bkc : g_bvc);
        dstB[e * II + m * 32 + tid] = s * scale;
    }
}

// =====================================================================
// Kernel 1: LayerNorm over C=256, one warp per token; output tf32-rounded.
// =====================================================================
__global__ __launch_bounds__(256) void k_ln(const float* __restrict__ x,
                                            const float* __restrict__ lw,
                                            const float* __restrict__ lb)
{
    int warp = threadIdx.x >> 5;
    int lane = threadIdx.x & 31;
    int tok  = (blockIdx.x << 3) + warp;

    const float4* xr = reinterpret_cast<const float4*>(x + (size_t)tok * CC);
    float4 v0 = xr[lane];
    float4 v1 = xr[lane + 32];

    float s  = v0.x + v0.y + v0.z + v0.w + v1.x + v1.y + v1.z + v1.w;
    float sq = v0.x*v0.x + v0.y*v0.y + v0.z*v0.z + v0.w*v0.w
             + v1.x*v1.x + v1.y*v1.y + v1.z*v1.z + v1.w*v1.w;
    #pragma unroll
    for (int off = 16; off >= 1; off >>= 1) {
        s  += __shfl_xor_sync(0xffffffffu, s,  off);
        sq += __shfl_xor_sync(0xffffffffu, sq, off);
    }
    float mean = s * (1.0f / 256.0f);
    float var  = sq * (1.0f / 256.0f) - mean * mean;
    float rstd = rsqrtf(var + 1e-5f);

    const float4* w4 = reinterpret_cast<const float4*>(lw);
    const float4* b4 = reinterpret_cast<const float4*>(lb);
    float4 w0 = w4[lane], w1 = w4[lane + 32];
    float4 b0 = b4[lane], b1 = b4[lane + 32];

    float4 o0, o1;
    o0.x = f2tf_f((v0.x - mean) * rstd * w0.x + b0.x);
    o0.y = f2tf_f((v0.y - mean) * rstd * w0.y + b0.y);
    o0.z = f2tf_f((v0.z - mean) * rstd * w0.z + b0.z);
    o0.w = f2tf_f((v0.w - mean) * rstd * w0.w + b0.w);
    o1.x = f2tf_f((v1.x - mean) * rstd * w1.x + b1.x);
    o1.y = f2tf_f((v1.y - mean) * rstd * w1.y + b1.y);
    o1.z = f2tf_f((v1.z - mean) * rstd * w1.z + b1.z);
    o1.w = f2tf_f((v1.w - mean) * rstd * w1.w + b1.w);

    float4* orow = reinterpret_cast<float4*>(g_xn + (size_t)tok * CC);
    orow[lane]      = o0;
    orow[lane + 32] = o1;
}

// =====================================================================
// tf32 GEMM tile via cp.async double buffer, BK=16, static smem (37.9 KB,
// 2 CTAs/SM). Out[128x128] = A[128x256] * W[256x128] + bias.
// =====================================================================
#define AS_ST 20
#define BS_ST 136
#define AS_SZ (128 * AS_ST)
#define BS_SZ (16 * BS_ST)

__device__ __forceinline__ void gemm_tf32(const float* __restrict__ A,
                                          const float* __restrict__ W,
                                          const float* __restrict__ bias,
                                          float* __restrict__ Out,
                                          int m0, int ncol0)
{
    __shared__ __align__(16) float As[2 * AS_SZ];   // [2][128][20]
    __shared__ __align__(16) float Bs[2 * BS_SZ];   // [2][16][136]

    const int tid  = threadIdx.x;
    const int lane = tid & 31;
    const int warp = tid >> 5;
    const int wm = (warp >> 2) << 6;
    const int wn = (warp & 3)  << 5;

    int arow[2], ac4[2], brow[2], bc4[2];
    #pragma unroll
    for (int it = 0; it < 2; ++it) {
        int pos = tid + (it << 8);
        arow[it] = pos >> 2;  ac4[it] = (pos & 3) << 2;
        brow[it] = pos >> 5;  bc4[it] = (pos & 31) << 2;
    }

    float acc[4][4][4];
    #pragma unroll
    for (int mt = 0; mt < 4; ++mt)
        #pragma unroll
        for (int nt = 0; nt < 4; ++nt)
            #pragma unroll
            for (int r = 0; r < 4; ++r) acc[mt][nt][r] = 0.0f;

    #pragma unroll
    for (int it = 0; it < 2; ++it) {
        cpa16(As + arow[it] * AS_ST + ac4[it],
              A + (size_t)(m0 + arow[it]) * 256 + ac4[it]);
        cpa16(Bs + brow[it] * BS_ST + bc4[it],
              W + (size_t)brow[it] * 256 + ncol0 + bc4[it]);
    }
    cpa_commit();

    for (int ch = 0; ch < 16; ++ch) {
        int buf = ch & 1;
        if (ch < 15) {
            int kc = (ch + 1) << 4;
            float* Asn = As + (buf ^ 1) * AS_SZ;
            float* Bsn = Bs + (buf ^ 1) * BS_SZ;
            #pragma unroll
            for (int it = 0; it < 2; ++it) {
                cpa16(Asn + arow[it] * AS_ST + ac4[it],
                      A + (size_t)(m0 + arow[it]) * 256 + kc + ac4[it]);
                cpa16(Bsn + brow[it] * BS_ST + bc4[it],
                      W + (size_t)(kc + brow[it]) * 256 + ncol0 + bc4[it]);
            }
            cpa_commit();
            cpa_wait<1>();
        } else {
            cpa_wait<0>();
        }
        __syncthreads();

        const float* Asb = As + buf * AS_SZ;
        const float* Bsb = Bs + buf * BS_SZ;

        #pragma unroll
        for (int ks = 0; ks < 2; ++ks) {
            int kr = (ks << 3) + (lane & 3);
            unsigned afr[4][4], bfr[4][2];
            #pragma unroll
            for (int mt = 0; mt < 4; ++mt) {
                int mc = wm + (mt << 4) + (lane >> 2);
                afr[mt][0] = __float_as_uint(Asb[mc * AS_ST + kr]);
                afr[mt][1] = __float_as_uint(Asb[(mc + 8) * AS_ST + kr]);
                afr[mt][2] = __float_as_uint(Asb[mc * AS_ST + kr + 4]);
                afr[mt][3] = __float_as_uint(Asb[(mc + 8) * AS_ST + kr + 4]);
            }
            #pragma unroll
            for (int nt = 0; nt < 4; ++nt) {
                int nc = wn + (nt << 3) + (lane >> 2);
                bfr[nt][0] = __float_as_uint(Bsb[kr * BS_ST + nc]);
                bfr[nt][1] = __float_as_uint(Bsb[(kr + 4) * BS_ST + nc]);
            }
            #pragma unroll
            for (int mt = 0; mt < 4; ++mt)
                #pragma unroll
                for (int nt = 0; nt < 4; ++nt)
                    mma_tf32(acc[mt][nt],
                             afr[mt][0], afr[mt][1], afr[mt][2], afr[mt][3],
                             bfr[nt][0], bfr[nt][1]);
        }
        __syncthreads();
    }

    #pragma unroll
    for (int mt = 0; mt < 4; ++mt) {
        int mrow = m0 + wm + (mt << 4) + (lane >> 2);
        #pragma unroll
        for (int nt = 0; nt < 4; ++nt) {
            int nc = ncol0 + wn + (nt << 3) + ((lane & 3) << 1);
            float b0 = bias[nc], b1 = bias[nc + 1];
            float2 r0, r1;
            r0.x = acc[mt][nt][0] + b0; r0.y = acc[mt][nt][1] + b1;
            r1.x = acc[mt][nt][2] + b0; r1.y = acc[mt][nt][3] + b1;
            *reinterpret_cast<float2*>(Out + (size_t)mrow * 256 + nc)       = r0;
            *reinterpret_cast<float2*>(Out + (size_t)(mrow + 8) * 256 + nc) = r1;
        }
    }
}

// =====================================================================
// Kernel 2: fused Q / K'0 / K'1 / V'0 / V'1 projection.
// grid = (8 mtiles, 10 = 5 outputs x 2 ntiles, 20 bl)
// =====================================================================
__global__ __launch_bounds__(256, 2) void k_gemm_qkv(const float* __restrict__ pe,
                                                     const float* __restrict__ bq)
{
    int bl = blockIdx.z;
    int t  = (int)pe[(size_t)bl * 3072 + 2];
    int sel   = blockIdx.y >> 1;             // 0..4
    int ncol0 = (blockIdx.y & 1) << 7;

    const float* W;
    const float* bias;
    float* out;
    switch (sel) {
        case 0: W = g_wq  + (size_t)t * CC * II;       bias = bq    + t * II;       out = g_q;             break;
        case 1: W = g_wkc + (size_t)t * CC * II;       bias = g_bkc + t * II;       out = g_kp;            break;
        case 2: W = g_wkc + (size_t)(2 + t) * CC * II; bias = g_bkc + (2 + t) * II; out = g_kp + TOKELEMS; break;
        case 3: W = g_wvc + (size_t)t * CC * II;       bias = g_bvc + t * II;       out = g_vp;            break;
        default:W = g_wvc + (size_t)(2 + t) * CC * II; bias = g_bvc + (2 + t) * II; out = g_vp + TOKELEMS; break;
    }

    gemm_tf32(g_xn + (size_t)bl * HW * CC,
              W, bias,
              out + (size_t)bl * HW * II,
              blockIdx.x << 7, ncol0);
}

// =====================================================================
// Kernel 3: attention (transforms pre-folded). 256 threads = 8 warps,
// one (b,m,hw) per warp. grid = B*M*HW/8 = 4096. Pure loads + warp dots
// + softmax; no smem weight staging.
// =====================================================================
__global__ __launch_bounds__(256) void k_attn(const int*   __restrict__ mask,
                                              const float* __restrict__ pe)
{
    __shared__ int ts_s[LL];

    int tid  = threadIdx.x;
    int lane = tid & 31;
    int w    = tid >> 5;
    int bidx = blockIdx.x;
    int hw   = ((bidx & 127) << 3) + w;
    int m    = (bidx >> 7) & 7;
    int b    = bidx >> 10;

    if (tid < LL) ts_s[tid] = (int)pe[(size_t)(b * LL + tid) * 3072 + 2];
    __syncthreads();

    int base_off = (m << 5) + lane;
    float qreg[LL], kp0[LL], kp1[LL], vp0[LL], vp1[LL];
    #pragma unroll
    for (int j = 0; j < LL; ++j) {
        size_t off = ((size_t)((b * LL + j) << 10) + hw) * II + base_off;
        qreg[j] = g_q [off];
        kp0[j]  = g_kp[off];
        kp1[j]  = g_kp[off + (size_t)TOKELEMS * 1];
        vp0[j]  = g_vp[off];
        vp1[j]  = g_vp[off + (size_t)TOKELEMS * 1];
    }

    // att[i][j] = q_i . k'_{j,t_i}  (D^-0.5 folded into k')
    float att[LL][LL];
    #pragma unroll
    for (int i = 0; i < LL; ++i) {
        int ti = ts_s[i];
        #pragma unroll
        for (int j = 0; j < LL; ++j) {
            float kv = ti ? kp1[j] : kp0[j];
            float part = qreg[i] * kv;
            part += __shfl_xor_sync(0xffffffffu, part, 16);
            part += __shfl_xor_sync(0xffffffffu, part, 8);
            part += __shfl_xor_sync(0xffffffffu, part, 4);
            part += __shfl_xor_sync(0xffffffffu, part, 2);
            part += __shfl_xor_sync(0xffffffffu, part, 1);
            att[i][j] = part;
        }
    }

    const int* mrow = mask + ((size_t)(b << 10) + hw) * 25;
    #pragma unroll
    for (int i = 0; i < LL; ++i) {
        float mx = -1e30f;
        #pragma unroll
        for (int j = 0; j < LL; ++j) {
            if (mrow[i * 5 + j] == 0) att[i][j] = -1e9f;
            mx = fmaxf(mx, att[i][j]);
        }
        float s = 0.f;
        #pragma unroll
        for (int j = 0; j < LL; ++j) {
            float e = __expf(att[i][j] - mx);
            att[i][j] = e;
            s += e;
        }
        float inv = 1.0f / s;
        int ti = ts_s[i];
        float o = 0.f;
        #pragma unroll
        for (int j = 0; j < LL; ++j) {
            float vv = ti ? vp1[j] : vp0[j];
            o = fmaf(att[i][j], vv, o);
        }
        size_t tok = (size_t)((b * LL + i) << 10) + hw;
        g_ao[tok * II + base_off] = f2tf_f(o * inv);
    }
}

// =====================================================================
// Kernel 4: output projection + bias -> final output. grid = (8,2,20)
// =====================================================================
__global__ __launch_bounds__(256, 2) void k_gemm_ao(const float* __restrict__ pe,
                                                    const float* __restrict__ ba,
                                                    float* __restrict__ out)
{
    int bl = blockIdx.z;
    int t  = (int)pe[(size_t)bl * 3072 + 2];
    gemm_tf32(g_ao + (size_t)bl * HW * II,
              g_wa + (size_t)t * II * CC,
              ba + (size_t)t * CC,
              out + (size_t)bl * HW * CC,
              blockIdx.x << 7, (blockIdx.y & 1) << 7);
}

// =====================================================================
extern "C" void kernel_launch(void* const* d_in, const int* in_sizes, int n_in,
                              void* d_out, int out_size)
{
    const float* x    = (const float*)d_in[0];
    const int*   mask = (const int*)  d_in[1];
    const float* pe   = (const float*)d_in[2];
    const float* lnw  = (const float*)d_in[3];
    const float* lnb  = (const float*)d_in[4];
    const float* Wq   = (const float*)d_in[5];
    const float* bq   = (const float*)d_in[6];
    const float* Wk   = (const float*)d_in[7];
    const float* bk   = (const float*)d_in[8];
    const float* Wv   = (const float*)d_in[9];
    const float* bv   = (const float*)d_in[10];
    const float* Wa   = (const float*)d_in[11];
    const float* ba   = (const float*)d_in[12];
    const float* ra   = (const float*)d_in[13];
    const float* rm   = (const float*)d_in[14];
    float* out = (float*)d_out;

    dim3 gw(128, 2);
    k_cvtw<<<gw, 256>>>(Wq, Wa);

    dim3 gc(4, 8, 2);
    k_comb<<<gc, 256>>>(Wk, bk, Wv, bv, ra, rm);

    k_ln<<<2560, 256>>>(x, lnw, lnb);

    dim3 g1(8, 10, 20);
    k_gemm_qkv<<<g1, 256>>>(pe, bq);

    k_attn<<<4096, 256>>>(mask, pe);

    dim3 g2(8, 2, 20);
    k_gemm_ao<<<g2, 256>>>(pe, ba, out);
}

// round 10
// speedup vs baseline: 1.4336x; 1.0472x over previous
#include <cuda_runtime.h>
#include <math.h>
#include <stdint.h>

// ---------------- problem constants ----------------
#define BB 4
#define LL 5
#define HW 1024          // HS*WS
#define CC 256
#define MM 8
#define DD 32
#define TT 2
#define II 256           // M*D
#define NTOK (BB*LL*HW)  // 20480
#define TOKELEMS (NTOK*CC)

// ---------------- scratch (static device globals) ----------------
__device__ __align__(16) float g_xn[TOKELEMS];      // tf32-rounded LN output
__device__ __align__(16) float g_q [TOKELEMS];      // fp32 q
__device__ __align__(16) float g_k [TOKELEMS];      // tf32-rounded k (incl bias)
__device__ __align__(16) float g_v [TOKELEMS];      // tf32-rounded v (incl bias)
__device__ __align__(16) float g_kp[2*TOKELEMS];    // transformed K, ti=0/1
__device__ __align__(16) float g_vp[2*TOKELEMS];    // transformed V, ti=0/1
__device__ __align__(16) float g_ao[TOKELEMS];      // tf32-rounded attn output
__device__ __align__(16) float g_wq[TT*CC*II];      // tf32-rounded weights [t][k][n]
__device__ __align__(16) float g_wk[TT*CC*II];
__device__ __align__(16) float g_wv[TT*CC*II];
__device__ __align__(16) float g_wa[TT*II*CC];
__device__ __align__(16) float g_rat[4*MM*DD*DD];   // tf32 RA*scale  [e][m][p][q]
__device__ __align__(16) float g_rmt[4*MM*DD*DD];   // tf32 RM^T      [e][m][o][p]

// ---------------- helpers ----------------
__device__ __forceinline__ unsigned f2tf(float f) {
    unsigned u;
    asm("cvt.rna.tf32.f32 %0, %1;" : "=r"(u) : "f"(f));
    return u;
}
__device__ __forceinline__ float f2tf_f(float f) { return __uint_as_float(f2tf(f)); }

__device__ __forceinline__ void mma_tf32(float c[4],
                                         unsigned a0, unsigned a1, unsigned a2, unsigned a3,
                                         unsigned b0, unsigned b1)
{
    asm volatile(
        "mma.sync.aligned.m16n8k8.row.col.f32.tf32.tf32.f32 "
        "{%0,%1,%2,%3}, {%4,%5,%6,%7}, {%8,%9}, {%0,%1,%2,%3};"
        : "+f"(c[0]), "+f"(c[1]), "+f"(c[2]), "+f"(c[3])
        : "r"(a0), "r"(a1), "r"(a2), "r"(a3), "r"(b0), "r"(b1));
}

__device__ __forceinline__ void cpa16(float* dst, const float* src) {
    unsigned d = (unsigned)__cvta_generic_to_shared(dst);
    asm volatile("cp.async.cg.shared.global [%0], [%1], 16;" :: "r"(d), "l"(src));
}
__device__ __forceinline__ void cpa_commit() {
    asm volatile("cp.async.commit_group;" ::: "memory");
}
template <int N> __device__ __forceinline__ void cpa_wait() {
    asm volatile("cp.async.wait_group %0;" :: "n"(N) : "memory");
}

// =====================================================================
// Kernel 0a: round the 4 weight tensors to tf32 (layout unchanged [t][k][n]).
// grid = (128, 4), 256 threads.
// =====================================================================
__global__ __launch_bounds__(256) void k_cvtw(const float* __restrict__ Wq,
                                              const float* __restrict__ Wk,
                                              const float* __restrict__ Wv,
                                              const float* __restrict__ Wa)
{
    const float* src;
    float* dst;
    switch (blockIdx.y) {
        case 0: src = Wq; dst = g_wq; break;
        case 1: src = Wk; dst = g_wk; break;
        case 2: src = Wv; dst = g_wv; break;
        default: src = Wa; dst = g_wa; break;
    }
    int idx = blockIdx.x * 256 + threadIdx.x;
    float4 v = reinterpret_cast<const float4*>(src)[idx];
    v.x = f2tf_f(v.x); v.y = f2tf_f(v.y); v.z = f2tf_f(v.z); v.w = f2tf_f(v.w);
    reinterpret_cast<float4*>(dst)[idx] = v;
}

// =====================================================================
// Kernel 0b: prep relation matrices.
//   g_rat[e][m][p][q] = f2tf( D^-0.5 * rel_att[e][m][p][q] )
//   g_rmt[e][m][o][p] = f2tf( rel_msg[e][m][p][o] )   (transposed)
// grid = (4 e, 8 m), 256 threads.
// =====================================================================
__global__ __launch_bounds__(256) void k_prepR(const float* __restrict__ ra,
                                               const float* __restrict__ rm)
{
    __shared__ float tile[32][33];
    int tid = threadIdx.x;
    size_t base = (size_t)(blockIdx.x * MM + blockIdx.y) * 1024;

    #pragma unroll
    for (int i = tid; i < 1024; i += 256)
        g_rat[base + i] = f2tf_f(0.17677669529663687f * ra[base + i]);

    #pragma unroll
    for (int i = tid; i < 1024; i += 256)
        tile[i >> 5][i & 31] = rm[base + i];
    __syncthreads();
    #pragma unroll
    for (int i = tid; i < 1024; i += 256) {
        int o = i >> 5, p = i & 31;
        g_rmt[base + i] = f2tf_f(tile[p][o]);
    }
}

// =====================================================================
// Kernel 1: LayerNorm, one warp per token; output tf32-rounded.
// =====================================================================
__global__ __launch_bounds__(256) void k_ln(const float* __restrict__ x,
                                            const float* __restrict__ lw,
                                            const float* __restrict__ lb)
{
    int warp = threadIdx.x >> 5;
    int lane = threadIdx.x & 31;
    int tok  = (blockIdx.x << 3) + warp;

    const float4* xr = reinterpret_cast<const float4*>(x + (size_t)tok * CC);
    float4 v0 = xr[lane];
    float4 v1 = xr[lane + 32];

    float s  = v0.x + v0.y + v0.z + v0.w + v1.x + v1.y + v1.z + v1.w;
    float sq = v0.x*v0.x + v0.y*v0.y + v0.z*v0.z + v0.w*v0.w
             + v1.x*v1.x + v1.y*v1.y + v1.z*v1.z + v1.w*v1.w;
    #pragma unroll
    for (int off = 16; off >= 1; off >>= 1) {
        s  += __shfl_xor_sync(0xffffffffu, s,  off);
        sq += __shfl_xor_sync(0xffffffffu, sq, off);
    }
    float mean = s * (1.0f / 256.0f);
    float var  = sq * (1.0f / 256.0f) - mean * mean;
    float rstd = rsqrtf(var + 1e-5f);

    const float4* w4 = reinterpret_cast<const float4*>(lw);
    const float4* b4 = reinterpret_cast<const float4*>(lb);
    float4 w0 = w4[lane], w1 = w4[lane + 32];
    float4 b0 = b4[lane], b1 = b4[lane + 32];

    float4 o0, o1;
    o0.x = f2tf_f((v0.x - mean) * rstd * w0.x + b0.x);
    o0.y = f2tf_f((v0.y - mean) * rstd * w0.y + b0.y);
    o0.z = f2tf_f((v0.z - mean) * rstd * w0.z + b0.z);
    o0.w = f2tf_f((v0.w - mean) * rstd * w0.w + b0.w);
    o1.x = f2tf_f((v1.x - mean) * rstd * w1.x + b1.x);
    o1.y = f2tf_f((v1.y - mean) * rstd * w1.y + b1.y);
    o1.z = f2tf_f((v1.z - mean) * rstd * w1.z + b1.z);
    o1.w = f2tf_f((v1.w - mean) * rstd * w1.w + b1.w);

    float4* orow = reinterpret_cast<float4*>(g_xn + (size_t)tok * CC);
    orow[lane]      = o0;
    orow[lane + 32] = o1;
}

// =====================================================================
// tf32 GEMM tile via cp.async double buffer, BK=16, static smem (37.9 KB,
// 2 CTAs/SM). Out[128x128] = A[128x256] * W[256x128] + bias.
// rnd != 0 -> tf32-round the stored output.
// =====================================================================
#define AS_ST 20
#define BS_ST 136
#define AS_SZ (128 * AS_ST)
#define BS_SZ (16 * BS_ST)

__device__ __forceinline__ void gemm_tf32(const float* __restrict__ A,
                                          const float* __restrict__ W,
                                          const float* __restrict__ bias,
                                          float* __restrict__ Out,
                                          int m0, int ncol0, int rnd)
{
    __shared__ __align__(16) float As[2 * AS_SZ];   // [2][128][20]
    __shared__ __align__(16) float Bs[2 * BS_SZ];   // [2][16][136]

    const int tid  = threadIdx.x;
    const int lane = tid & 31;
    const int warp = tid >> 5;
    const int wm = (warp >> 2) << 6;
    const int wn = (warp & 3)  << 5;

    int arow[2], ac4[2], brow[2], bc4[2];
    #pragma unroll
    for (int it = 0; it < 2; ++it) {
        int pos = tid + (it << 8);
        arow[it] = pos >> 2;  ac4[it] = (pos & 3) << 2;
        brow[it] = pos >> 5;  bc4[it] = (pos & 31) << 2;
    }

    float acc[4][4][4];
    #pragma unroll
    for (int mt = 0; mt < 4; ++mt)
        #pragma unroll
        for (int nt = 0; nt < 4; ++nt)
            #pragma unroll
            for (int r = 0; r < 4; ++r) acc[mt][nt][r] = 0.0f;

    #pragma unroll
    for (int it = 0; it < 2; ++it) {
        cpa16(As + arow[it] * AS_ST + ac4[it],
              A + (size_t)(m0 + arow[it]) * 256 + ac4[it]);
        cpa16(Bs + brow[it] * BS_ST + bc4[it],
              W + (size_t)brow[it] * 256 + ncol0 + bc4[it]);
    }
    cpa_commit();

    for (int ch = 0; ch < 16; ++ch) {
        int buf = ch & 1;
        if (ch < 15) {
            int kc = (ch + 1) << 4;
            float* Asn = As + (buf ^ 1) * AS_SZ;
            float* Bsn = Bs + (buf ^ 1) * BS_SZ;
            #pragma unroll
            for (int it = 0; it < 2; ++it) {
                cpa16(Asn + arow[it] * AS_ST + ac4[it],
                      A + (size_t)(m0 + arow[it]) * 256 + kc + ac4[it]);
                cpa16(Bsn + brow[it] * BS_ST + bc4[it],
                      W + (size_t)(kc + brow[it]) * 256 + ncol0 + bc4[it]);
            }
            cpa_commit();
            cpa_wait<1>();
        } else {
            cpa_wait<0>();
        }
        __syncthreads();

        const float* Asb = As + buf * AS_SZ;
        const float* Bsb = Bs + buf * BS_SZ;

        #pragma unroll
        for (int ks = 0; ks < 2; ++ks) {
            int kr = (ks << 3) + (lane & 3);
            unsigned afr[4][4], bfr[4][2];
            #pragma unroll
            for (int mt = 0; mt < 4; ++mt) {
                int mc = wm + (mt << 4) + (lane >> 2);
                afr[mt][0] = __float_as_uint(Asb[mc * AS_ST + kr]);
                afr[mt][1] = __float_as_uint(Asb[(mc + 8) * AS_ST + kr]);
                afr[mt][2] = __float_as_uint(Asb[mc * AS_ST + kr + 4]);
                afr[mt][3] = __float_as_uint(Asb[(mc + 8) * AS_ST + kr + 4]);
            }
            #pragma unroll
            for (int nt = 0; nt < 4; ++nt) {
                int nc = wn + (nt << 3) + (lane >> 2);
                bfr[nt][0] = __float_as_uint(Bsb[kr * BS_ST + nc]);
                bfr[nt][1] = __float_as_uint(Bsb[(kr + 4) * BS_ST + nc]);
            }
            #pragma unroll
            for (int mt = 0; mt < 4; ++mt)
                #pragma unroll
                for (int nt = 0; nt < 4; ++nt)
                    mma_tf32(acc[mt][nt],
                             afr[mt][0], afr[mt][1], afr[mt][2], afr[mt][3],
                             bfr[nt][0], bfr[nt][1]);
        }
        __syncthreads();
    }

    #pragma unroll
    for (int mt = 0; mt < 4; ++mt) {
        int mrow = m0 + wm + (mt << 4) + (lane >> 2);
        #pragma unroll
        for (int nt = 0; nt < 4; ++nt) {
            int nc = ncol0 + wn + (nt << 3) + ((lane & 3) << 1);
            float b0 = bias[nc], b1 = bias[nc + 1];
            float2 r0, r1;
            r0.x = acc[mt][nt][0] + b0; r0.y = acc[mt][nt][1] + b1;
            r1.x = acc[mt][nt][2] + b0; r1.y = acc[mt][nt][3] + b1;
            if (rnd) {
                r0.x = f2tf_f(r0.x); r0.y = f2tf_f(r0.y);
                r1.x = f2tf_f(r1.x); r1.y = f2tf_f(r1.y);
            }
            *reinterpret_cast<float2*>(Out + (size_t)mrow * 256 + nc)       = r0;
            *reinterpret_cast<float2*>(Out + (size_t)(mrow + 8) * 256 + nc) = r1;
        }
    }
}

// =====================================================================
// Kernel 2: q/k/v projection only (transforms moved to k_xform).
// grid = (8 mtiles, 6 = 3 outputs x 2 ncol halves, 20 bl)
// =====================================================================
__global__ __launch_bounds__(256, 2) void k_gemm_qkv(const float* __restrict__ pe,
                                                     const float* __restrict__ bq,
                                                     const float* __restrict__ bk,
                                                     const float* __restrict__ bv)
{
    int bl = blockIdx.z;
    int t  = (int)pe[(size_t)bl * 3072 + 2];
    int sel   = blockIdx.y >> 1;
    int ncol0 = (blockIdx.y & 1) << 7;

    const float* W;
    const float* bias;
    float* out;
    int rnd;
    if (sel == 0)      { W = g_wq; bias = bq; out = g_q; rnd = 0; }
    else if (sel == 1) { W = g_wk; bias = bk; out = g_k; rnd = 1; }
    else               { W = g_wv; bias = bv; out = g_v; rnd = 1; }

    gemm_tf32(g_xn + (size_t)bl * HW * CC,
              W + (size_t)t * CC * II,
              bias + (size_t)t * II,
              out + (size_t)bl * HW * II,
              blockIdx.x << 7, ncol0, rnd);
}

// =====================================================================
// Kernel 2b: relation transform via small tensor-core GEMMs.
//   K'_{ti}[tok][m*32+p] = sum_q RA[ti*2+tj][m][p][q] * k[tok][m*32+q]
//   V'_{ti}[tok][m*32+o] = sum_p RM[ti*2+tj][m][p][o] * v[tok][m*32+o... p]
// CTA = 64 tokens, loops m=0..7. 8 warps: warps 0-3 K-side, 4-7 V-side,
// each warp 16 token-rows x 32 cols x {ti0,ti1}. grid = (16 ttile, 20 bl).
// =====================================================================
__global__ __launch_bounds__(256) void k_xform(const float* __restrict__ pe)
{
    __shared__ __align__(16) float sk[64 * 36];
    __shared__ __align__(16) float sv[64 * 36];
    __shared__ __align__(16) float sra[2][32 * 36];
    __shared__ __align__(16) float srm[2][32 * 36];

    int tid  = threadIdx.x;
    int lane = tid & 31;
    int wid  = tid >> 5;
    int bl   = blockIdx.y;
    int tj   = (int)pe[(size_t)bl * 3072 + 2];
    int tok0 = (bl << 10) + ((int)blockIdx.x << 6);

    int side = wid >> 2;            // 0 = K (att), 1 = V (msg)
    int wmt  = wid & 3;             // 16-row block within 64 tokens
    const float* Asm = side ? sv : sk;
    const float* src = side ? g_v : g_k;
    float* Og        = side ? g_vp : g_kp;

    for (int m = 0; m < 8; ++m) {
        __syncthreads();            // previous head's smem reads done
        // stage k,v 64x32 slices (2 x 16B chunks per thread per tensor)
        #pragma unroll
        for (int it = 0; it < 2; ++it) {
            int c   = tid + (it << 8);     // 0..511
            int row = c >> 3;
            int kc  = (c & 7) << 2;
            cpa16(sk + row * 36 + kc, g_k + (size_t)(tok0 + row) * 256 + m * 32 + kc);
            cpa16(sv + row * 36 + kc, g_v + (size_t)(tok0 + row) * 256 + m * 32 + kc);
        }
        // stage 4 R matrices (RA ti0/1, RM^T ti0/1), 1 x 16B chunk each
        {
            int row = tid >> 3;
            int kc  = (tid & 7) << 2;
            #pragma unroll
            for (int ti = 0; ti < 2; ++ti) {
                size_t rb = (size_t)(((ti * 2 + tj) * MM + m)) * 1024 + tid * 4;
                cpa16(&sra[ti][row * 36 + kc], g_rat + rb);
                cpa16(&srm[ti][row * 36 + kc], g_rmt + rb);
            }
        }
        cpa_commit();
        cpa_wait<0>();
        __syncthreads();

        float acc[2][4][4];
        #pragma unroll
        for (int ti = 0; ti < 2; ++ti)
            #pragma unroll
            for (int nt = 0; nt < 4; ++nt)
                #pragma unroll
                for (int r = 0; r < 4; ++r) acc[ti][nt][r] = 0.0f;

        #pragma unroll
        for (int ks = 0; ks < 4; ++ks) {
            int k0 = (ks << 3) + (lane & 3);
            int ar = (wmt << 4) + (lane >> 2);
            unsigned a0 = __float_as_uint(Asm[ar * 36 + k0]);
            unsigned a1 = __float_as_uint(Asm[(ar + 8) * 36 + k0]);
            unsigned a2 = __float_as_uint(Asm[ar * 36 + k0 + 4]);
            unsigned a3 = __float_as_uint(Asm[(ar + 8) * 36 + k0 + 4]);
            #pragma unroll
            for (int nt = 0; nt < 4; ++nt) {
                int br = (nt << 3) + (lane >> 2);
                #pragma unroll
                for (int ti = 0; ti < 2; ++ti) {
                    const float* B = side ? srm[ti] : sra[ti];
                    unsigned b0 = __float_as_uint(B[br * 36 + k0]);
                    unsigned b1 = __float_as_uint(B[br * 36 + k0 + 4]);
                    mma_tf32(acc[ti][nt], a0, a1, a2, a3, b0, b1);
                }
            }
        }

        // store: rows = tokens, cols = m*32 + nt*8 + 2*(lane&3)
        #pragma unroll
        for (int ti = 0; ti < 2; ++ti) {
            float* Ob = Og + (size_t)ti * TOKELEMS;
            #pragma unroll
            for (int nt = 0; nt < 4; ++nt) {
                int col = (m << 5) + (nt << 3) + ((lane & 3) << 1);
                int r0  = tok0 + (wmt << 4) + (lane >> 2);
                float2 w0, w1;
                w0.x = acc[ti][nt][0]; w0.y = acc[ti][nt][1];
                w1.x = acc[ti][nt][2]; w1.y = acc[ti][nt][3];
                *reinterpret_cast<float2*>(Ob + (size_t)r0 * 256 + col)       = w0;
                *reinterpret_cast<float2*>(Ob + (size_t)(r0 + 8) * 256 + col) = w1;
            }
        }
    }
}

// =====================================================================
// Kernel 3: attention (transforms pre-applied). One (b,m,hw) per warp.
// grid = 4096, 256 threads. Unchanged from R8.
// =====================================================================
__global__ __launch_bounds__(256) void k_attn(const int*   __restrict__ mask,
                                              const float* __restrict__ pe)
{
    __shared__ int ts_s[LL];

    int tid  = threadIdx.x;
    int lane = tid & 31;
    int w    = tid >> 5;
    int bidx = blockIdx.x;
    int hw   = ((bidx & 127) << 3) + w;
    int m    = (bidx >> 7) & 7;
    int b    = bidx >> 10;

    if (tid < LL) ts_s[tid] = (int)pe[(size_t)(b * LL + tid) * 3072 + 2];
    __syncthreads();

    int base_off = (m << 5) + lane;
    float qreg[LL], kp0[LL], kp1[LL], vp0[LL], vp1[LL];
    #pragma unroll
    for (int j = 0; j < LL; ++j) {
        size_t off = ((size_t)((b * LL + j) << 10) + hw) * II + base_off;
        qreg[j] = g_q [off];
        kp0[j]  = g_kp[off];
        kp1[j]  = g_kp[off + (size_t)TOKELEMS];
        vp0[j]  = g_vp[off];
        vp1[j]  = g_vp[off + (size_t)TOKELEMS];
    }

    float att[LL][LL];
    #pragma unroll
    for (int i = 0; i < LL; ++i) {
        int ti = ts_s[i];
        #pragma unroll
        for (int j = 0; j < LL; ++j) {
            float kv = ti ? kp1[j] : kp0[j];
            float part = qreg[i] * kv;
            part += __shfl_xor_sync(0xffffffffu, part, 16);
            part += __shfl_xor_sync(0xffffffffu, part, 8);
            part += __shfl_xor_sync(0xffffffffu, part, 4);
            part += __shfl_xor_sync(0xffffffffu, part, 2);
            part += __shfl_xor_sync(0xffffffffu, part, 1);
            att[i][j] = part;
        }
    }

    const int* mrow = mask + ((size_t)(b << 10) + hw) * 25;
    #pragma unroll
    for (int i = 0; i < LL; ++i) {
        float mx = -1e30f;
        #pragma unroll
        for (int j = 0; j < LL; ++j) {
            if (mrow[i * 5 + j] == 0) att[i][j] = -1e9f;
            mx = fmaxf(mx, att[i][j]);
        }
        float s = 0.f;
        #pragma unroll
        for (int j = 0; j < LL; ++j) {
            float e = __expf(att[i][j] - mx);
            att[i][j] = e;
            s += e;
        }
        float inv = 1.0f / s;
        int ti = ts_s[i];
        float o = 0.f;
        #pragma unroll
        for (int j = 0; j < LL; ++j) {
            float vv = ti ? vp1[j] : vp0[j];
            o = fmaf(att[i][j], vv, o);
        }
        size_t tok = (size_t)((b * LL + i) << 10) + hw;
        g_ao[tok * II + base_off] = f2tf_f(o * inv);
    }
}

// =====================================================================
// Kernel 4: output projection + bias -> final output. grid = (8,2,20)
// =====================================================================
__global__ __launch_bounds__(256, 2) void k_gemm_ao(const float* __restrict__ pe,
                                                    const float* __restrict__ ba,
                                                    float* __restrict__ out)
{
    int bl = blockIdx.z;
    int t  = (int)pe[(size_t)bl * 3072 + 2];
    gemm_tf32(g_ao + (size_t)bl * HW * II,
              g_wa + (size_t)t * II * CC,
              ba + (size_t)t * CC,
              out + (size_t)bl * HW * CC,
              blockIdx.x << 7, (blockIdx.y & 1) << 7, 0);
}

// =====================================================================
extern "C" void kernel_launch(void* const* d_in, const int* in_sizes, int n_in,
                              void* d_out, int out_size)
{
    const float* x    = (const float*)d_in[0];
    const int*   mask = (const int*)  d_in[1];
    const float* pe   = (const float*)d_in[2];
    const float* lnw  = (const float*)d_in[3];
    const float* lnb  = (const float*)d_in[4];
    const float* Wq   = (const float*)d_in[5];
    const float* bq   = (const float*)d_in[6];
    const float* Wk   = (const float*)d_in[7];
    const float* bk   = (const float*)d_in[8];
    const float* Wv   = (const float*)d_in[9];
    const float* bv   = (const float*)d_in[10];
    const float* Wa   = (const float*)d_in[11];
    const float* ba   = (const float*)d_in[12];
    const float* ra   = (const float*)d_in[13];
    const float* rm   = (const float*)d_in[14];
    float* out = (float*)d_out;

    dim3 gw(128, 4);
    k_cvtw<<<gw, 256>>>(Wq, Wk, Wv, Wa);

    dim3 gr(4, 8);
    k_prepR<<<gr, 256>>>(ra, rm);

    k_ln<<<2560, 256>>>(x, lnw, lnb);

    dim3 g1(8, 6, 20);
    k_gemm_qkv<<<g1, 256>>>(pe, bq, bk, bv);

    dim3 gx(16, 20);
    k_xform<<<gx, 256>>>(pe);

    k_attn<<<4096, 256>>>(mask, pe);

    dim3 g2(8, 2, 20);
    k_gemm_ao<<<g2, 256>>>(pe, ba, out);
}

// round 11
// speedup vs baseline: 1.4959x; 1.0435x over previous
#include <cuda_runtime.h>
#include <math.h>
#include <stdint.h>

// ---------------- problem constants ----------------
#define BB 4
#define LL 5
#define HW 1024          // HS*WS
#define CC 256
#define MM 8
#define DD 32
#define TT 2
#define II 256           // M*D
#define NTOK (BB*LL*HW)  // 20480
#define TOKELEMS (NTOK*CC)

// ---------------- scratch (static device globals) ----------------
__device__ __align__(16) float g_xn[TOKELEMS];      // tf32-rounded LN output
__device__ __align__(16) float g_q [TOKELEMS];      // fp32 q
__device__ __align__(16) float g_k [TOKELEMS];      // tf32-rounded k (incl bias)
__device__ __align__(16) float g_v [TOKELEMS];      // tf32-rounded v (incl bias)
__device__ __align__(16) float g_kp[2*TOKELEMS];    // transformed K, ti=0/1
__device__ __align__(16) float g_vp[2*TOKELEMS];    // transformed V, ti=0/1
__device__ __align__(16) float g_ao[TOKELEMS];      // tf32-rounded attn output
__device__ __align__(16) float g_wq[TT*CC*II];      // tf32-rounded weights [t][k][n]
__device__ __align__(16) float g_wk[TT*CC*II];
__device__ __align__(16) float g_wv[TT*CC*II];
__device__ __align__(16) float g_wa[TT*II*CC];
__device__ __align__(16) float g_rat[4*MM*DD*DD];   // tf32 RA*scale  [e][m][p][q]
__device__ __align__(16) float g_rmt[4*MM*DD*DD];   // tf32 RM^T      [e][m][o][p]

// ---------------- helpers ----------------
__device__ __forceinline__ unsigned f2tf(float f) {
    unsigned u;
    asm("cvt.rna.tf32.f32 %0, %1;" : "=r"(u) : "f"(f));
    return u;
}
__device__ __forceinline__ float f2tf_f(float f) { return __uint_as_float(f2tf(f)); }

__device__ __forceinline__ void mma_tf32(float c[4],
                                         unsigned a0, unsigned a1, unsigned a2, unsigned a3,
                                         unsigned b0, unsigned b1)
{
    asm volatile(
        "mma.sync.aligned.m16n8k8.row.col.f32.tf32.tf32.f32 "
        "{%0,%1,%2,%3}, {%4,%5,%6,%7}, {%8,%9}, {%0,%1,%2,%3};"
        : "+f"(c[0]), "+f"(c[1]), "+f"(c[2]), "+f"(c[3])
        : "r"(a0), "r"(a1), "r"(a2), "r"(a3), "r"(b0), "r"(b1));
}

__device__ __forceinline__ void cpa16(float* dst, const float* src) {
    unsigned d = (unsigned)__cvta_generic_to_shared(dst);
    asm volatile("cp.async.cg.shared.global [%0], [%1], 16;" :: "r"(d), "l"(src));
}
__device__ __forceinline__ void cpa_commit() {
    asm volatile("cp.async.commit_group;" ::: "memory");
}
template <int N> __device__ __forceinline__ void cpa_wait() {
    asm volatile("cp.async.wait_group %0;" :: "n"(N) : "memory");
}

// =====================================================================
// Kernel 0 (merged prep): blocks [0,512) weight tf32 rounding,
// [512,544) relation-matrix prep, [544,3104) LayerNorm.
// All independent; all feed the qkv GEMM.
// =====================================================================
__global__ __launch_bounds__(256) void k_prep(const float* __restrict__ Wq,
                                              const float* __restrict__ Wk,
                                              const float* __restrict__ Wv,
                                              const float* __restrict__ Wa,
                                              const float* __restrict__ ra,
                                              const float* __restrict__ rm,
                                              const float* __restrict__ x,
                                              const float* __restrict__ lw,
                                              const float* __restrict__ lb)
{
    __shared__ float tile[32][33];
    int bx  = blockIdx.x;
    int tid = threadIdx.x;

    if (bx < 512) {
        // ---- weight rounding: 4 tensors x 128 blocks ----
        const float* src;
        float* dst;
        switch (bx >> 7) {
            case 0: src = Wq; dst = g_wq; break;
            case 1: src = Wk; dst = g_wk; break;
            case 2: src = Wv; dst = g_wv; break;
            default: src = Wa; dst = g_wa; break;
        }
        int idx = (bx & 127) * 256 + tid;
        float4 v = reinterpret_cast<const float4*>(src)[idx];
        v.x = f2tf_f(v.x); v.y = f2tf_f(v.y); v.z = f2tf_f(v.z); v.w = f2tf_f(v.w);
        reinterpret_cast<float4*>(dst)[idx] = v;
        return;
    }

    if (bx < 544) {
        // ---- relation prep: 32 blocks = (e=4, m=8) ----
        int e = (bx - 512) >> 3;
        int m = (bx - 512) & 7;
        size_t base = (size_t)(e * MM + m) * 1024;

        #pragma unroll
        for (int i = tid; i < 1024; i += 256)
            g_rat[base + i] = f2tf_f(0.17677669529663687f * ra[base + i]);

        #pragma unroll
        for (int i = tid; i < 1024; i += 256)
            tile[(i >> 5) & 31][i & 31] = rm[base + i];
        __syncthreads();
        #pragma unroll
        for (int i = tid; i < 1024; i += 256) {
            int o = i >> 5, p = i & 31;
            g_rmt[base + i] = f2tf_f(tile[p][o]);
        }
        return;
    }

    // ---- LayerNorm: one warp per token ----
    int warp = tid >> 5;
    int lane = tid & 31;
    int tok  = ((bx - 544) << 3) + warp;

    const float4* xr = reinterpret_cast<const float4*>(x + (size_t)tok * CC);
    float4 v0 = xr[lane];
    float4 v1 = xr[lane + 32];

    float s  = v0.x + v0.y + v0.z + v0.w + v1.x + v1.y + v1.z + v1.w;
    float sq = v0.x*v0.x + v0.y*v0.y + v0.z*v0.z + v0.w*v0.w
             + v1.x*v1.x + v1.y*v1.y + v1.z*v1.z + v1.w*v1.w;
    #pragma unroll
    for (int off = 16; off >= 1; off >>= 1) {
        s  += __shfl_xor_sync(0xffffffffu, s,  off);
        sq += __shfl_xor_sync(0xffffffffu, sq, off);
    }
    float mean = s * (1.0f / 256.0f);
    float var  = sq * (1.0f / 256.0f) - mean * mean;
    float rstd = rsqrtf(var + 1e-5f);

    const float4* w4 = reinterpret_cast<const float4*>(lw);
    const float4* b4 = reinterpret_cast<const float4*>(lb);
    float4 w0 = w4[lane], w1 = w4[lane + 32];
    float4 b0 = b4[lane], b1 = b4[lane + 32];

    float4 o0, o1;
    o0.x = f2tf_f((v0.x - mean) * rstd * w0.x + b0.x);
    o0.y = f2tf_f((v0.y - mean) * rstd * w0.y + b0.y);
    o0.z = f2tf_f((v0.z - mean) * rstd * w0.z + b0.z);
    o0.w = f2tf_f((v0.w - mean) * rstd * w0.w + b0.w);
    o1.x = f2tf_f((v1.x - mean) * rstd * w1.x + b1.x);
    o1.y = f2tf_f((v1.y - mean) * rstd * w1.y + b1.y);
    o1.z = f2tf_f((v1.z - mean) * rstd * w1.z + b1.z);
    o1.w = f2tf_f((v1.w - mean) * rstd * w1.w + b1.w);

    float4* orow = reinterpret_cast<float4*>(g_xn + (size_t)tok * CC);
    orow[lane]      = o0;
    orow[lane + 32] = o1;
}

// =====================================================================
// tf32 GEMM tile via cp.async double buffer, BK=16, static smem (37.9 KB,
// 2 CTAs/SM). Out[128x128] = A[128x256] * W[256x128] + bias.
// rnd != 0 -> tf32-round the stored output.  (unchanged, proven)
// =====================================================================
#define AS_ST 20
#define BS_ST 136
#define AS_SZ (128 * AS_ST)
#define BS_SZ (16 * BS_ST)

__device__ __forceinline__ void gemm_tf32(const float* __restrict__ A,
                                          const float* __restrict__ W,
                                          const float* __restrict__ bias,
                                          float* __restrict__ Out,
                                          int m0, int ncol0, int rnd)
{
    __shared__ __align__(16) float As[2 * AS_SZ];   // [2][128][20]
    __shared__ __align__(16) float Bs[2 * BS_SZ];   // [2][16][136]

    const int tid  = threadIdx.x;
    const int lane = tid & 31;
    const int warp = tid >> 5;
    const int wm = (warp >> 2) << 6;
    const int wn = (warp & 3)  << 5;

    int arow[2], ac4[2], brow[2], bc4[2];
    #pragma unroll
    for (int it = 0; it < 2; ++it) {
        int pos = tid + (it << 8);
        arow[it] = pos >> 2;  ac4[it] = (pos & 3) << 2;
        brow[it] = pos >> 5;  bc4[it] = (pos & 31) << 2;
    }

    float acc[4][4][4];
    #pragma unroll
    for (int mt = 0; mt < 4; ++mt)
        #pragma unroll
        for (int nt = 0; nt < 4; ++nt)
            #pragma unroll
            for (int r = 0; r < 4; ++r) acc[mt][nt][r] = 0.0f;

    #pragma unroll
    for (int it = 0; it < 2; ++it) {
        cpa16(As + arow[it] * AS_ST + ac4[it],
              A + (size_t)(m0 + arow[it]) * 256 + ac4[it]);
        cpa16(Bs + brow[it] * BS_ST + bc4[it],
              W + (size_t)brow[it] * 256 + ncol0 + bc4[it]);
    }
    cpa_commit();

    for (int ch = 0; ch < 16; ++ch) {
        int buf = ch & 1;
        if (ch < 15) {
            int kc = (ch + 1) << 4;
            float* Asn = As + (buf ^ 1) * AS_SZ;
            float* Bsn = Bs + (buf ^ 1) * BS_SZ;
            #pragma unroll
            for (int it = 0; it < 2; ++it) {
                cpa16(Asn + arow[it] * AS_ST + ac4[it],
                      A + (size_t)(m0 + arow[it]) * 256 + kc + ac4[it]);
                cpa16(Bsn + brow[it] * BS_ST + bc4[it],
                      W + (size_t)(kc + brow[it]) * 256 + ncol0 + bc4[it]);
            }
            cpa_commit();
            cpa_wait<1>();
        } else {
            cpa_wait<0>();
        }
        __syncthreads();

        const float* Asb = As + buf * AS_SZ;
        const float* Bsb = Bs + buf * BS_SZ;

        #pragma unroll
        for (int ks = 0; ks < 2; ++ks) {
            int kr = (ks << 3) + (lane & 3);
            unsigned afr[4][4], bfr[4][2];
            #pragma unroll
            for (int mt = 0; mt < 4; ++mt) {
                int mc = wm + (mt << 4) + (lane >> 2);
                afr[mt][0] = __float_as_uint(Asb[mc * AS_ST + kr]);
                afr[mt][1] = __float_as_uint(Asb[(mc + 8) * AS_ST + kr]);
                afr[mt][2] = __float_as_uint(Asb[mc * AS_ST + kr + 4]);
                afr[mt][3] = __float_as_uint(Asb[(mc + 8) * AS_ST + kr + 4]);
            }
            #pragma unroll
            for (int nt = 0; nt < 4; ++nt) {
                int nc = wn + (nt << 3) + (lane >> 2);
                bfr[nt][0] = __float_as_uint(Bsb[kr * BS_ST + nc]);
                bfr[nt][1] = __float_as_uint(Bsb[(kr + 4) * BS_ST + nc]);
            }
            #pragma unroll
            for (int mt = 0; mt < 4; ++mt)
                #pragma unroll
                for (int nt = 0; nt < 4; ++nt)
                    mma_tf32(acc[mt][nt],
                             afr[mt][0], afr[mt][1], afr[mt][2], afr[mt][3],
                             bfr[nt][0], bfr[nt][1]);
        }
        __syncthreads();
    }

    #pragma unroll
    for (int mt = 0; mt < 4; ++mt) {
        int mrow = m0 + wm + (mt << 4) + (lane >> 2);
        #pragma unroll
        for (int nt = 0; nt < 4; ++nt) {
            int nc = ncol0 + wn + (nt << 3) + ((lane & 3) << 1);
            float b0 = bias[nc], b1 = bias[nc + 1];
            float2 r0, r1;
            r0.x = acc[mt][nt][0] + b0; r0.y = acc[mt][nt][1] + b1;
            r1.x = acc[mt][nt][2] + b0; r1.y = acc[mt][nt][3] + b1;
            if (rnd) {
                r0.x = f2tf_f(r0.x); r0.y = f2tf_f(r0.y);
                r1.x = f2tf_f(r1.x); r1.y = f2tf_f(r1.y);
            }
            *reinterpret_cast<float2*>(Out + (size_t)mrow * 256 + nc)       = r0;
            *reinterpret_cast<float2*>(Out + (size_t)(mrow + 8) * 256 + nc) = r1;
        }
    }
}

// =====================================================================
// Kernel 2: q/k/v projection. grid = (8 mtiles, 6, 20 bl)
// =====================================================================
__global__ __launch_bounds__(256, 2) void k_gemm_qkv(const float* __restrict__ pe,
                                                     const float* __restrict__ bq,
                                                     const float* __restrict__ bk,
                                                     const float* __restrict__ bv)
{
    int bl = blockIdx.z;
    int t  = (int)pe[(size_t)bl * 3072 + 2];
    int sel   = blockIdx.y >> 1;
    int ncol0 = (blockIdx.y & 1) << 7;

    const float* W;
    const float* bias;
    float* out;
    int rnd;
    if (sel == 0)      { W = g_wq; bias = bq; out = g_q; rnd = 0; }
    else if (sel == 1) { W = g_wk; bias = bk; out = g_k; rnd = 1; }
    else               { W = g_wv; bias = bv; out = g_v; rnd = 1; }

    gemm_tf32(g_xn + (size_t)bl * HW * CC,
              W + (size_t)t * CC * II,
              bias + (size_t)t * II,
              out + (size_t)bl * HW * II,
              blockIdx.x << 7, ncol0, rnd);
}

// =====================================================================
// Kernel 2b (v2): relation transform. One (64-token tile, head) per CTA:
// grid = (320 ttile, 8 m) = 2560 CTAs. Only R in smem (18KB -> 2+ CTA/SM);
// k/v A-fragments loaded directly from gmem. Warps 0-3: K side (16 tokens
// each), warps 4-7: V side. No head loop, single sync.
// =====================================================================
__global__ __launch_bounds__(256) void k_xform(const float* __restrict__ pe)
{
    __shared__ __align__(16) float sra[2][32 * 36];   // [ti][p*36+q]  RA'
    __shared__ __align__(16) float srm[2][32 * 36];   // [ti][o*36+p]  RM^T

    int tid  = threadIdx.x;
    int lane = tid & 31;
    int wid  = tid >> 5;
    int m    = blockIdx.y;
    int tok0 = (int)blockIdx.x << 6;
    int bl   = tok0 >> 10;
    int tj   = (int)pe[(size_t)bl * 3072 + 2];

    // stage the 4 R matrices (RA ti0/1, RM^T ti0/1): 1024 x 16B chunks
    #pragma unroll
    for (int c = 0; c < 4; ++c) {
        int chunk = tid + (c << 8);        // 0..1023
        int mat   = chunk >> 8;            // 0..3: {ra0, ra1, rm0, rm1}
        int off   = chunk & 255;           // 16B chunk within matrix
        int row   = off >> 3;
        int col4  = (off & 7) << 2;
        int ti    = mat & 1;
        int kind  = mat >> 1;
        const float* src = (kind ? g_rmt : g_rat)
                         + (((size_t)((ti * 2 + tj) * MM + m)) << 10) + off * 4;
        float* dst = (kind ? &srm[ti][0] : &sra[ti][0]) + row * 36 + col4;
        cpa16(dst, src);
    }
    cpa_commit();
    cpa_wait<0>();
    __syncthreads();

    int side = wid >> 2;                   // 0 = K (att), 1 = V (msg)
    int wmt  = wid & 3;
    const float* srcg = side ? g_v : g_k;
    float* dstg       = side ? g_vp : g_kp;

    // A-fragments direct from gmem (rows = tokens, cols = head slice)
    int arow = tok0 + (wmt << 4) + (lane >> 2);
    const float* abase = srcg + (size_t)arow * 256 + (m << 5) + (lane & 3);
    unsigned af[4][4];
    #pragma unroll
    for (int ks = 0; ks < 4; ++ks) {
        af[ks][0] = __float_as_uint(abase[ks * 8]);
        af[ks][1] = __float_as_uint(abase[8 * 256 + ks * 8]);
        af[ks][2] = __float_as_uint(abase[ks * 8 + 4]);
        af[ks][3] = __float_as_uint(abase[8 * 256 + ks * 8 + 4]);
    }

    float acc[2][4][4];
    #pragma unroll
    for (int ti = 0; ti < 2; ++ti)
        #pragma unroll
        for (int nt = 0; nt < 4; ++nt)
            #pragma unroll
            for (int r = 0; r < 4; ++r) acc[ti][nt][r] = 0.0f;

    #pragma unroll
    for (int ks = 0; ks < 4; ++ks) {
        int k0 = (ks << 3) + (lane & 3);
        #pragma unroll
        for (int nt = 0; nt < 4; ++nt) {
            int br = (nt << 3) + (lane >> 2);
            #pragma unroll
            for (int ti = 0; ti < 2; ++ti) {
                const float* B = side ? &srm[ti][0] : &sra[ti][0];
                unsigned b0 = __float_as_uint(B[br * 36 + k0]);
                unsigned b1 = __float_as_uint(B[br * 36 + k0 + 4]);
                mma_tf32(acc[ti][nt], af[ks][0], af[ks][1], af[ks][2], af[ks][3],
                         b0, b1);
            }
        }
    }

    #pragma unroll
    for (int ti = 0; ti < 2; ++ti) {
        float* Ob = dstg + (size_t)ti * TOKELEMS;
        #pragma unroll
        for (int nt = 0; nt < 4; ++nt) {
            int col = (m << 5) + (nt << 3) + ((lane & 3) << 1);
            int r0  = tok0 + (wmt << 4) + (lane >> 2);
            float2 w0, w1;
            w0.x = acc[ti][nt][0]; w0.y = acc[ti][nt][1];
            w1.x = acc[ti][nt][2]; w1.y = acc[ti][nt][3];
            *reinterpret_cast<float2*>(Ob + (size_t)r0 * 256 + col)       = w0;
            *reinterpret_cast<float2*>(Ob + (size_t)(r0 + 8) * 256 + col) = w1;
        }
    }
}

// =====================================================================
// Kernel 3: attention (transforms pre-applied). One (b,m,hw) per warp.
// grid = 4096, 256 threads. Unchanged.
// =====================================================================
__global__ __launch_bounds__(256) void k_attn(const int*   __restrict__ mask,
                                              const float* __restrict__ pe)
{
    __shared__ int ts_s[LL];

    int tid  = threadIdx.x;
    int lane = tid & 31;
    int w    = tid >> 5;
    int bidx = blockIdx.x;
    int hw   = ((bidx & 127) << 3) + w;
    int m    = (bidx >> 7) & 7;
    int b    = bidx >> 10;

    if (tid < LL) ts_s[tid] = (int)pe[(size_t)(b * LL + tid) * 3072 + 2];
    __syncthreads();

    int base_off = (m << 5) + lane;
    float qreg[LL], kp0[LL], kp1[LL], vp0[LL], vp1[LL];
    #pragma unroll
    for (int j = 0; j < LL; ++j) {
        size_t off = ((size_t)((b * LL + j) << 10) + hw) * II + base_off;
        qreg[j] = g_q [off];
        kp0[j]  = g_kp[off];
        kp1[j]  = g_kp[off + (size_t)TOKELEMS];
        vp0[j]  = g_vp[off];
        vp1[j]  = g_vp[off + (size_t)TOKELEMS];
    }

    float att[LL][LL];
    #pragma unroll
    for (int i = 0; i < LL; ++i) {
        int ti = ts_s[i];
        #pragma unroll
        for (int j = 0; j < LL; ++j) {
            float kv = ti ? kp1[j] : kp0[j];
            float part = qreg[i] * kv;
            part += __shfl_xor_sync(0xffffffffu, part, 16);
            part += __shfl_xor_sync(0xffffffffu, part, 8);
            part += __shfl_xor_sync(0xffffffffu, part, 4);
            part += __shfl_xor_sync(0xffffffffu, part, 2);
            part += __shfl_xor_sync(0xffffffffu, part, 1);
            att[i][j] = part;
        }
    }

    const int* mrow = mask + ((size_t)(b << 10) + hw) * 25;
    #pragma unroll
    for (int i = 0; i < LL; ++i) {
        float mx = -1e30f;
        #pragma unroll
        for (int j = 0; j < LL; ++j) {
            if (mrow[i * 5 + j] == 0) att[i][j] = -1e9f;
            mx = fmaxf(mx, att[i][j]);
        }
        float s = 0.f;
        #pragma unroll
        for (int j = 0; j < LL; ++j) {
            float e = __expf(att[i][j] - mx);
            att[i][j] = e;
            s += e;
        }
        float inv = 1.0f / s;
        int ti = ts_s[i];
        float o = 0.f;
        #pragma unroll
        for (int j = 0; j < LL; ++j) {
            float vv = ti ? vp1[j] : vp0[j];
            o = fmaf(att[i][j], vv, o);
        }
        size_t tok = (size_t)((b * LL + i) << 10) + hw;
        g_ao[tok * II + base_off] = f2tf_f(o * inv);
    }
}

// =====================================================================
// Kernel 4: output projection + bias -> final output. grid = (8,2,20)
// =====================================================================
__global__ __launch_bounds__(256, 2) void k_gemm_ao(const float* __restrict__ pe,
                                                    const float* __restrict__ ba,
                                                    float* __restrict__ out)
{
    int bl = blockIdx.z;
    int t  = (int)pe[(size_t)bl * 3072 + 2];
    gemm_tf32(g_ao + (size_t)bl * HW * II,
              g_wa + (size_t)t * II * CC,
              ba + (size_t)t * CC,
              out + (size_t)bl * HW * CC,
              blockIdx.x << 7, (blockIdx.y & 1) << 7, 0);
}

// =====================================================================
extern "C" void kernel_launch(void* const* d_in, const int* in_sizes, int n_in,
                              void* d_out, int out_size)
{
    const float* x    = (const float*)d_in[0];
    const int*   mask = (const int*)  d_in[1];
    const float* pe   = (const float*)d_in[2];
    const float* lnw  = (const float*)d_in[3];
    const float* lnb  = (const float*)d_in[4];
    const float* Wq   = (const float*)d_in[5];
    const float* bq   = (const float*)d_in[6];
    const float* Wk   = (const float*)d_in[7];
    const float* bk   = (const float*)d_in[8];
    const float* Wv   = (const float*)d_in[9];
    const float* bv   = (const float*)d_in[10];
    const float* Wa   = (const float*)d_in[11];
    const float* ba   = (const float*)d_in[12];
    const float* ra   = (const float*)d_in[13];
    const float* rm   = (const float*)d_in[14];
    float* out = (float*)d_out;

    // merged prep: weights round (512) + relation prep (32) + LN (2560)
    k_prep<<<3104, 256>>>(Wq, Wk, Wv, Wa, ra, rm, x, lnw, lnb);

    dim3 g1(8, 6, 20);
    k_gemm_qkv<<<g1, 256>>>(pe, bq, bk, bv);

    dim3 gx(320, 8);
    k_xform<<<gx, 256>>>(pe);

    k_attn<<<4096, 256>>>(mask, pe);

    dim3 g2(8, 2, 20);
    k_gemm_ao<<<g2, 256>>>(pe, ba, out);
}

// round 12
// speedup vs baseline: 1.5501x; 1.0362x over previous
#include <cuda_runtime.h>
#include <math.h>
#include <stdint.h>

// ---------------- problem constants ----------------
#define BB 4
#define LL 5
#define HW 1024          // HS*WS
#define CC 256
#define MM 8
#define DD 32
#define TT 2
#define II 256           // M*D
#define NTOK (BB*LL*HW)  // 20480
#define TOKELEMS (NTOK*CC)

// K-dim permutation: pos(k) = (k&~7) + 2*(k&3) + ((k>>2)&1)
// Makes fragment pairs (k, k+4) adjacent -> LDS.64 in the GEMM.
#define PERM8(c) ((((c) & 3) << 1) | (((c) >> 2) & 1))
#define POSK(k)  (((k) & ~7) | PERM8((k) & 7))

// ---------------- scratch (static device globals) ----------------
__device__ __align__(16) float g_xn[TOKELEMS];      // tf32 LN output, K-permuted
__device__ __align__(16) float g_q [TOKELEMS];      // fp32 q (plain layout)
__device__ __align__(16) float g_k [TOKELEMS];      // tf32 k (plain layout)
__device__ __align__(16) float g_v [TOKELEMS];      // tf32 v (plain layout)
__device__ __align__(16) float g_kp[2*TOKELEMS];    // transformed K, ti=0/1
__device__ __align__(16) float g_vp[2*TOKELEMS];    // transformed V, ti=0/1
__device__ __align__(16) float g_ao[TOKELEMS];      // tf32 attn out, K-permuted
__device__ __align__(16) float g_wq[TT*CC*II];      // tf32 W^T [t][n][pos(k)]
__device__ __align__(16) float g_wk[TT*CC*II];
__device__ __align__(16) float g_wv[TT*CC*II];
__device__ __align__(16) float g_wa[TT*II*CC];
__device__ __align__(16) float g_rat[4*MM*DD*DD];   // tf32 RA*scale  [e][m][p][q]
__device__ __align__(16) float g_rmt[4*MM*DD*DD];   // tf32 RM^T      [e][m][o][p]

// ---------------- helpers ----------------
__device__ __forceinline__ unsigned f2tf(float f) {
    unsigned u;
    asm("cvt.rna.tf32.f32 %0, %1;" : "=r"(u) : "f"(f));
    return u;
}
__device__ __forceinline__ float f2tf_f(float f) { return __uint_as_float(f2tf(f)); }

__device__ __forceinline__ void mma_tf32(float c[4],
                                         unsigned a0, unsigned a1, unsigned a2, unsigned a3,
                                         unsigned b0, unsigned b1)
{
    asm volatile(
        "mma.sync.aligned.m16n8k8.row.col.f32.tf32.tf32.f32 "
        "{%0,%1,%2,%3}, {%4,%5,%6,%7}, {%8,%9}, {%0,%1,%2,%3};"
        : "+f"(c[0]), "+f"(c[1]), "+f"(c[2]), "+f"(c[3])
        : "r"(a0), "r"(a1), "r"(a2), "r"(a3), "r"(b0), "r"(b1));
}

__device__ __forceinline__ void cpa16(float* dst, const float* src) {
    unsigned d = (unsigned)__cvta_generic_to_shared(dst);
    asm volatile("cp.async.cg.shared.global [%0], [%1], 16;" :: "r"(d), "l"(src));
}
__device__ __forceinline__ void cpa_commit() {
    asm volatile("cp.async.commit_group;" ::: "memory");
}
template <int N> __device__ __forceinline__ void cpa_wait() {
    asm volatile("cp.async.wait_group %0;" :: "n"(N) : "memory");
}

// =====================================================================
// Kernel 0 (merged prep):
//   blocks [0,512)    : weight transpose + K-perm + tf32 round
//                       (tensor = bx>>7, t = (bx>>6)&1, 32x32 tile = bx&63)
//   blocks [512,544)  : relation-matrix prep
//   blocks [544,3104) : LayerNorm (permuted-gather, permuted store)
// =====================================================================
__global__ __launch_bounds__(256) void k_prep(const float* __restrict__ Wq,
                                              const float* __restrict__ Wk,
                                              const float* __restrict__ Wv,
                                              const float* __restrict__ Wa,
                                              const float* __restrict__ ra,
                                              const float* __restrict__ rm,
                                              const float* __restrict__ x,
                                              const float* __restrict__ lw,
                                              const float* __restrict__ lb)
{
    __shared__ float tile[32][33];
    int bx  = blockIdx.x;
    int tid = threadIdx.x;

    if (bx < 512) {
        // ---- weight transpose [t][k][n] -> [t][n][pos(k)], tf32 round ----
        int tsr  = bx >> 7;            // 0..3: Wq, Wk, Wv, Wa
        int tt   = (bx >> 6) & 1;      // type slice
        int tl   = bx & 63;            // 8x8 tiles of 32x32
        int k0   = (tl >> 3) << 5;
        int n0   = (tl & 7) << 5;
        const float* src;
        float* dst;
        switch (tsr) {
            case 0: src = Wq; dst = g_wq; break;
            case 1: src = Wk; dst = g_wk; break;
            case 2: src = Wv; dst = g_wv; break;
            default: src = Wa; dst = g_wa; break;
        }
        src += (size_t)tt * 65536;
        dst += (size_t)tt * 65536;

        int c  = tid & 31;
        int r0 = tid >> 5;
        #pragma unroll
        for (int rr = r0; rr < 32; rr += 8)
            tile[rr][c] = src[(size_t)(k0 + rr) * 256 + n0 + c];
        __syncthreads();
        int pc = (c & 24) | PERM8(c & 7);
        #pragma unroll
        for (int rr = r0; rr < 32; rr += 8)
            dst[(size_t)(n0 + rr) * 256 + k0 + pc] = f2tf_f(tile[c][rr]);
        return;
    }

    if (bx < 544) {
        // ---- relation prep: 32 blocks = (e=4, m=8) ----
        int e = (bx - 512) >> 3;
        int m = (bx - 512) & 7;
        size_t base = (size_t)(e * MM + m) * 1024;

        #pragma unroll
        for (int i = tid; i < 1024; i += 256)
            g_rat[base + i] = f2tf_f(0.17677669529663687f * ra[base + i]);

        #pragma unroll
        for (int i = tid; i < 1024; i += 256)
            tile[(i >> 5) & 31][i & 31] = rm[base + i];
        __syncthreads();
        #pragma unroll
        for (int i = tid; i < 1024; i += 256) {
            int o = i >> 5, p = i & 31;
            g_rmt[base + i] = f2tf_f(tile[p][o]);
        }
        return;
    }

    // ---- LayerNorm: one warp per token, K-permuted gather + store ----
    int warp = tid >> 5;
    int lane = tid & 31;
    int tok  = ((bx - 544) << 3) + warp;
    const float* xrow = x + (size_t)tok * CC;

    // Each lane owns pos-quads at 4*lane and 4*(lane+32).
    // quad Q: group g = Q>>1, half q = Q&1; values (orig order in perm slots):
    //   a = orig(8g+2q, 8g+2q+1), b = orig(8g+2q+4, 8g+2q+5)
    //   pos-quad = (a.x, b.x, a.y, b.y)
    float2 xa0, xb0, xa1, xb1;
    {
        int Q0 = lane,      g0 = Q0 >> 1, q0 = Q0 & 1;
        int Q1 = lane + 32, g1 = Q1 >> 1, q1 = Q1 & 1;
        xa0 = *(const float2*)(xrow + g0 * 8 + 2 * q0);
        xb0 = *(const float2*)(xrow + g0 * 8 + 2 * q0 + 4);
        xa1 = *(const float2*)(xrow + g1 * 8 + 2 * q1);
        xb1 = *(const float2*)(xrow + g1 * 8 + 2 * q1 + 4);
    }

    float s  = xa0.x + xa0.y + xb0.x + xb0.y + xa1.x + xa1.y + xb1.x + xb1.y;
    float sq = xa0.x*xa0.x + xa0.y*xa0.y + xb0.x*xb0.x + xb0.y*xb0.y
             + xa1.x*xa1.x + xa1.y*xa1.y + xb1.x*xb1.x + xb1.y*xb1.y;
    #pragma unroll
    for (int off = 16; off >= 1; off >>= 1) {
        s  += __shfl_xor_sync(0xffffffffu, s,  off);
        sq += __shfl_xor_sync(0xffffffffu, sq, off);
    }
    float mean = s * (1.0f / 256.0f);
    float var  = sq * (1.0f / 256.0f) - mean * mean;
    float rstd = rsqrtf(var + 1e-5f);

    float2 wa0, wb0, wa1, wb1, ba0, bb0, ba1, bb1;
    {
        int Q0 = lane,      g0 = Q0 >> 1, q0 = Q0 & 1;
        int Q1 = lane + 32, g1 = Q1 >> 1, q1 = Q1 & 1;
        wa0 = *(const float2*)(lw + g0 * 8 + 2 * q0);
        wb0 = *(const float2*)(lw + g0 * 8 + 2 * q0 + 4);
        wa1 = *(const float2*)(lw + g1 * 8 + 2 * q1);
        wb1 = *(const float2*)(lw + g1 * 8 + 2 * q1 + 4);
        ba0 = *(const float2*)(lb + g0 * 8 + 2 * q0);
        bb0 = *(const float2*)(lb + g0 * 8 + 2 * q0 + 4);
        ba1 = *(const float2*)(lb + g1 * 8 + 2 * q1);
        bb1 = *(const float2*)(lb + g1 * 8 + 2 * q1 + 4);
    }

    float4 o0, o1;
    o0.x = f2tf_f((xa0.x - mean) * rstd * wa0.x + ba0.x);
    o0.y = f2tf_f((xb0.x - mean) * rstd * wb0.x + bb0.x);
    o0.z = f2tf_f((xa0.y - mean) * rstd * wa0.y + ba0.y);
    o0.w = f2tf_f((xb0.y - mean) * rstd * wb0.y + bb0.y);
    o1.x = f2tf_f((xa1.x - mean) * rstd * wa1.x + ba1.x);
    o1.y = f2tf_f((xb1.x - mean) * rstd * wb1.x + bb1.x);
    o1.z = f2tf_f((xa1.y - mean) * rstd * wa1.y + ba1.y);
    o1.w = f2tf_f((xb1.y - mean) * rstd * wb1.y + bb1.y);

    float4* orow = reinterpret_cast<float4*>(g_xn + (size_t)tok * CC);
    orow[lane]      = o0;
    orow[lane + 32] = o1;
}

// =====================================================================
// tf32 GEMM tile, cp.async double buffer, BK=16, K-pair interleaved
// layout -> all fragment loads are LDS.64, pad-24 conflict-free.
// A: [m][pos(k)] row-major (lda=256).  Wt: [n][pos(k)] (ld=256).
// Out[128x128] = A * Wt^T + bias.  smem = 48KB exactly, 2 CTAs/SM.
// =====================================================================
#define TS_ST 24
#define TS_SZ (128 * TS_ST)     // 3072 floats per stage

__device__ __forceinline__ void gemm_tf32(const float* __restrict__ A,
                                          const float* __restrict__ Wt,
                                          const float* __restrict__ bias,
                                          float* __restrict__ Out,
                                          int m0, int ncol0, int rnd)
{
    __shared__ __align__(16) float As[2 * TS_SZ];   // [2][128][24]
    __shared__ __align__(16) float Bs[2 * TS_SZ];   // [2][128][24]

    const int tid  = threadIdx.x;
    const int lane = tid & 31;
    const int warp = tid >> 5;
    const int wm = (warp >> 2) << 6;
    const int wn = (warp & 3)  << 5;

    // loader: both A and B tiles are 128 rows x 16 k-floats (4x16B chunks/row)
    int lrow[2], lc4[2];
    #pragma unroll
    for (int it = 0; it < 2; ++it) {
        int pos = tid + (it << 8);
        lrow[it] = pos >> 2;  lc4[it] = (pos & 3) << 2;
    }

    float acc[4][4][4];
    #pragma unroll
    for (int mt = 0; mt < 4; ++mt)
        #pragma unroll
        for (int nt = 0; nt < 4; ++nt)
            #pragma unroll
            for (int r = 0; r < 4; ++r) acc[mt][nt][r] = 0.0f;

    #pragma unroll
    for (int it = 0; it < 2; ++it) {
        cpa16(As + lrow[it] * TS_ST + lc4[it],
              A  + (size_t)(m0 + lrow[it]) * 256 + lc4[it]);
        cpa16(Bs + lrow[it] * TS_ST + lc4[it],
              Wt + (size_t)(ncol0 + lrow[it]) * 256 + lc4[it]);
    }
    cpa_commit();

    for (int ch = 0; ch < 16; ++ch) {
        int buf = ch & 1;
        if (ch < 15) {
            int kc = (ch + 1) << 4;
            float* Asn = As + (buf ^ 1) * TS_SZ;
            float* Bsn = Bs + (buf ^ 1) * TS_SZ;
            #pragma unroll
            for (int it = 0; it < 2; ++it) {
                cpa16(Asn + lrow[it] * TS_ST + lc4[it],
                      A  + (size_t)(m0 + lrow[it]) * 256 + kc + lc4[it]);
                cpa16(Bsn + lrow[it] * TS_ST + lc4[it],
                      Wt + (size_t)(ncol0 + lrow[it]) * 256 + kc + lc4[it]);
            }
            cpa_commit();
            cpa_wait<1>();
        } else {
            cpa_wait<0>();
        }
        __syncthreads();

        const float* Asb = As + buf * TS_SZ;
        const float* Bsb = Bs + buf * TS_SZ;

        #pragma unroll
        for (int ks = 0; ks < 2; ++ks) {
            int kp2 = (ks << 3) + ((lane & 3) << 1);   // pos of (k, k+4) pair
            float2 afr[4][2];
            float2 bfr[4];
            #pragma unroll
            for (int mt = 0; mt < 4; ++mt) {
                const float* pA = Asb + (wm + (mt << 4) + (lane >> 2)) * TS_ST + kp2;
                afr[mt][0] = *reinterpret_cast<const float2*>(pA);
                afr[mt][1] = *reinterpret_cast<const float2*>(pA + 8 * TS_ST);
            }
            #pragma unroll
            for (int nt = 0; nt < 4; ++nt) {
                const float* pB = Bsb + (wn + (nt << 3) + (lane >> 2)) * TS_ST + kp2;
                bfr[nt] = *reinterpret_cast<const float2*>(pB);
            }
            #pragma unroll
            for (int mt = 0; mt < 4; ++mt)
                #pragma unroll
                for (int nt = 0; nt < 4; ++nt)
                    mma_tf32(acc[mt][nt],
                             __float_as_uint(afr[mt][0].x),   // a0 (k)
                             __float_as_uint(afr[mt][1].x),   // a1 (row+8, k)
                             __float_as_uint(afr[mt][0].y),   // a2 (k+4)
                             __float_as_uint(afr[mt][1].y),   // a3 (row+8, k+4)
                             __float_as_uint(bfr[nt].x),      // b0 (k)
                             __float_as_uint(bfr[nt].y));     // b1 (k+4)
        }
        __syncthreads();
    }

    #pragma unroll
    for (int mt = 0; mt < 4; ++mt) {
        int mrow = m0 + wm + (mt << 4) + (lane >> 2);
        #pragma unroll
        for (int nt = 0; nt < 4; ++nt) {
            int nc = ncol0 + wn + (nt << 3) + ((lane & 3) << 1);
            float b0 = bias[nc], b1 = bias[nc + 1];
            float2 r0, r1;
            r0.x = acc[mt][nt][0] + b0; r0.y = acc[mt][nt][1] + b1;
            r1.x = acc[mt][nt][2] + b0; r1.y = acc[mt][nt][3] + b1;
            if (rnd) {
                r0.x = f2tf_f(r0.x); r0.y = f2tf_f(r0.y);
                r1.x = f2tf_f(r1.x); r1.y = f2tf_f(r1.y);
            }
            *reinterpret_cast<float2*>(Out + (size_t)mrow * 256 + nc)       = r0;
            *reinterpret_cast<float2*>(Out + (size_t)(mrow + 8) * 256 + nc) = r1;
        }
    }
}

// =====================================================================
// Kernel 2: q/k/v projection. grid = (8 mtiles, 6, 20 bl)
// =====================================================================
__global__ __launch_bounds__(256, 2) void k_gemm_qkv(const float* __restrict__ pe,
                                                     const float* __restrict__ bq,
                                                     const float* __restrict__ bk,
                                                     const float* __restrict__ bv)
{
    int bl = blockIdx.z;
    int t  = (int)pe[(size_t)bl * 3072 + 2];
    int sel   = blockIdx.y >> 1;
    int ncol0 = (blockIdx.y & 1) << 7;

    const float* W;
    const float* bias;
    float* out;
    int rnd;
    if (sel == 0)      { W = g_wq; bias = bq; out = g_q; rnd = 0; }
    else if (sel == 1) { W = g_wk; bias = bk; out = g_k; rnd = 1; }
    else               { W = g_wv; bias = bv; out = g_v; rnd = 1; }

    gemm_tf32(g_xn + (size_t)bl * HW * CC,
              W + (size_t)t * CC * II,
              bias + (size_t)t * II,
              out + (size_t)bl * HW * II,
              blockIdx.x << 7, ncol0, rnd);
}

// =====================================================================
// Kernel 2b: relation transform (unchanged from R11 — proven).
// grid = (320 ttile, 8 m).
// =====================================================================
__global__ __launch_bounds__(256) void k_xform(const float* __restrict__ pe)
{
    __shared__ __align__(16) float sra[2][32 * 36];
    __shared__ __align__(16) float srm[2][32 * 36];

    int tid  = threadIdx.x;
    int lane = tid & 31;
    int wid  = tid >> 5;
    int m    = blockIdx.y;
    int tok0 = (int)blockIdx.x << 6;
    int bl   = tok0 >> 10;
    int tj   = (int)pe[(size_t)bl * 3072 + 2];

    #pragma unroll
    for (int c = 0; c < 4; ++c) {
        int chunk = tid + (c << 8);
        int mat   = chunk >> 8;
        int off   = chunk & 255;
        int row   = off >> 3;
        int col4  = (off & 7) << 2;
        int ti    = mat & 1;
        int kind  = mat >> 1;
        const float* src = (kind ? g_rmt : g_rat)
                         + (((size_t)((ti * 2 + tj) * MM + m)) << 10) + off * 4;
        float* dst = (kind ? &srm[ti][0] : &sra[ti][0]) + row * 36 + col4;
        cpa16(dst, src);
    }
    cpa_commit();
    cpa_wait<0>();
    __syncthreads();

    int side = wid >> 2;
    int wmt  = wid & 3;
    const float* srcg = side ? g_v : g_k;
    float* dstg       = side ? g_vp : g_kp;

    int arow = tok0 + (wmt << 4) + (lane >> 2);
    const float* abase = srcg + (size_t)arow * 256 + (m << 5) + (lane & 3);
    unsigned af[4][4];
    #pragma unroll
    for (int ks = 0; ks < 4; ++ks) {
        af[ks][0] = __float_as_uint(abase[ks * 8]);
        af[ks][1] = __float_as_uint(abase[8 * 256 + ks * 8]);
        af[ks][2] = __float_as_uint(abase[ks * 8 + 4]);
        af[ks][3] = __float_as_uint(abase[8 * 256 + ks * 8 + 4]);
    }

    float acc[2][4][4];
    #pragma unroll
    for (int ti = 0; ti < 2; ++ti)
        #pragma unroll
        for (int nt = 0; nt < 4; ++nt)
            #pragma unroll
            for (int r = 0; r < 4; ++r) acc[ti][nt][r] = 0.0f;

    #pragma unroll
    for (int ks = 0; ks < 4; ++ks) {
        int k0 = (ks << 3) + (lane & 3);
        #pragma unroll
        for (int nt = 0; nt < 4; ++nt) {
            int br = (nt << 3) + (lane >> 2);
            #pragma unroll
            for (int ti = 0; ti < 2; ++ti) {
                const float* B = side ? &srm[ti][0] : &sra[ti][0];
                unsigned b0 = __float_as_uint(B[br * 36 + k0]);
                unsigned b1 = __float_as_uint(B[br * 36 + k0 + 4]);
                mma_tf32(acc[ti][nt], af[ks][0], af[ks][1], af[ks][2], af[ks][3],
                         b0, b1);
            }
        }
    }

    #pragma unroll
    for (int ti = 0; ti < 2; ++ti) {
        float* Ob = dstg + (size_t)ti * TOKELEMS;
        #pragma unroll
        for (int nt = 0; nt < 4; ++nt) {
            int col = (m << 5) + (nt << 3) + ((lane & 3) << 1);
            int r0  = tok0 + (wmt << 4) + (lane >> 2);
            float2 w0, w1;
            w0.x = acc[ti][nt][0]; w0.y = acc[ti][nt][1];
            w1.x = acc[ti][nt][2]; w1.y = acc[ti][nt][3];
            *reinterpret_cast<float2*>(Ob + (size_t)r0 * 256 + col)       = w0;
            *reinterpret_cast<float2*>(Ob + (size_t)(r0 + 8) * 256 + col) = w1;
        }
    }
}

// =====================================================================
// Kernel 3: attention. One (b,m,hw) per warp, grid = 4096.
// Warp-uniform branch on ti (no per-element selects), 32-bit offsets,
// output stored with K-permuted columns (feeds ao GEMM).
// =====================================================================
__global__ __launch_bounds__(256) void k_attn(const int*   __restrict__ mask,
                                              const float* __restrict__ pe)
{
    __shared__ int ts_s[LL];

    int tid  = threadIdx.x;
    int lane = tid & 31;
    int w    = tid >> 5;
    int bidx = blockIdx.x;
    int hw   = ((bidx & 127) << 3) + w;
    int m    = (bidx >> 7) & 7;
    int b    = bidx >> 10;

    if (tid < LL) ts_s[tid] = (int)pe[(size_t)(b * LL + tid) * 3072 + 2];
    __syncthreads();

    int base_off = (m << 5) + lane;
    int tokbase  = ((b * LL) << 10) + hw;            // token index of l=0
    float qreg[LL], kp0[LL], kp1[LL], vp0[LL], vp1[LL];
    #pragma unroll
    for (int j = 0; j < LL; ++j) {
        unsigned off = (unsigned)(tokbase + (j << 10)) * 256u + (unsigned)base_off;
        qreg[j] = g_q [off];
        kp0[j]  = g_kp[off];
        kp1[j]  = g_kp[(size_t)off + (size_t)TOKELEMS];
        vp0[j]  = g_vp[off];
        vp1[j]  = g_vp[(size_t)off + (size_t)TOKELEMS];
    }

    float att[LL][LL];
    #pragma unroll
    for (int i = 0; i < LL; ++i) {
        float q = qreg[i];
        if (ts_s[i]) {                                // warp-uniform branch
            #pragma unroll
            for (int j = 0; j < LL; ++j) att[i][j] = q * kp1[j];
        } else {
            #pragma unroll
            for (int j = 0; j < LL; ++j) att[i][j] = q * kp0[j];
        }
        #pragma unroll
        for (int j = 0; j < LL; ++j) {
            float part = att[i][j];
            part += __shfl_xor_sync(0xffffffffu, part, 16);
            part += __shfl_xor_sync(0xffffffffu, part, 8);
            part += __shfl_xor_sync(0xffffffffu, part, 4);
            part += __shfl_xor_sync(0xffffffffu, part, 2);
            part += __shfl_xor_sync(0xffffffffu, part, 1);
            att[i][j] = part;
        }
    }

    // K-permuted output column for the ao GEMM
    int plane = (lane & 24) | PERM8(lane & 7);
    int obase = (m << 5) + plane;

    const int* mrow = mask + ((size_t)(b << 10) + hw) * 25;
    #pragma unroll
    for (int i = 0; i < LL; ++i) {
        float mx = -1e30f;
        #pragma unroll
        for (int j = 0; j < LL; ++j) {
            if (mrow[i * 5 + j] == 0) att[i][j] = -1e9f;
            mx = fmaxf(mx, att[i][j]);
        }
        float s = 0.f;
        #pragma unroll
        for (int j = 0; j < LL; ++j) {
            float e = __expf(att[i][j] - mx);
            att[i][j] = e;
            s += e;
        }
        float inv = 1.0f / s;
        float o = 0.f;
        if (ts_s[i]) {
            #pragma unroll
            for (int j = 0; j < LL; ++j) o = fmaf(att[i][j], vp1[j], o);
        } else {
            #pragma unroll
            for (int j = 0; j < LL; ++j) o = fmaf(att[i][j], vp0[j], o);
        }
        unsigned tok = (unsigned)(tokbase + (i << 10));
        g_ao[(size_t)tok * 256 + obase] = f2tf_f(o * inv);
    }
}

// =====================================================================
// Kernel 4: output projection + bias -> final output. grid = (8,2,20)
// =====================================================================
__global__ __launch_bounds__(256, 2) void k_gemm_ao(const float* __restrict__ pe,
                                                    const float* __restrict__ ba,
                                                    float* __restrict__ out)
{
    int bl = blockIdx.z;
    int t  = (int)pe[(size_t)bl * 3072 + 2];
    gemm_tf32(g_ao + (size_t)bl * HW * II,
              g_wa + (size_t)t * II * CC,
              ba + (size_t)t * CC,
              out + (size_t)bl * HW * CC,
              blockIdx.x << 7, (blockIdx.y & 1) << 7, 0);
}

// =====================================================================
extern "C" void kernel_launch(void* const* d_in, const int* in_sizes, int n_in,
                              void* d_out, int out_size)
{
    const float* x    = (const float*)d_in[0];
    const int*   mask = (const int*)  d_in[1];
    const float* pe   = (const float*)d_in[2];
    const float* lnw  = (const float*)d_in[3];
    const float* lnb  = (const float*)d_in[4];
    const float* Wq   = (const float*)d_in[5];
    const float* bq   = (const float*)d_in[6];
    const float* Wk   = (const float*)d_in[7];
    const float* bk   = (const float*)d_in[8];
    const float* Wv   = (const float*)d_in[9];
    const float* bv   = (const float*)d_in[10];
    const float* Wa   = (const float*)d_in[11];
    const float* ba   = (const float*)d_in[12];
    const float* ra   = (const float*)d_in[13];
    const float* rm   = (const float*)d_in[14];
    float* out = (float*)d_out;

    // merged prep: weight transpose+perm (512) + relation prep (32) + LN (2560)
    k_prep<<<3104, 256>>>(Wq, Wk, Wv, Wa, ra, rm, x, lnw, lnb);

    dim3 g1(8, 6, 20);
    k_gemm_qkv<<<g1, 256>>>(pe, bq, bk, bv);

    dim3 gx(320, 8);
    k_xform<<<gx, 256>>>(pe);

    k_attn<<<4096, 256>>>(mask, pe);

    dim3 g2(8, 2, 20);
    k_gemm_ao<<<g2, 256>>>(pe, ba, out);
}